// round 15
// baseline (speedup 1.0000x reference)
#include <cuda_runtime.h>
#include <cuda_fp16.h>
#include <cstdint>

#define N_NODES 50000
#define N_EDGES 800000
#define N_REL 6
#define N_LAYERS 8
#define D 256
#define NUM_GRAPHS 512
#define KREL 1536
#define KTOT 1792
#define NPAIR (N_NODES * N_REL)        /* 300000 */
#define SCAN_B 512
#define NSB ((NPAIR + SCAN_B - 1) / SCAN_B)   /* 586 */

// M-split: 296 CTAs x 128 rows (2 exact waves) + 127 CTAs x 96 rows (1 partial wave)
#define TILES4 296
#define OFF4   (TILES4 * 128)   /* 37888 */
#define TILES3 127

// ---------------- scratch (static __device__ — no allocations) ----------------
__device__ __half g_Af[(size_t)N_NODES * KREL];   // aggregated A, single fp16 limb
__device__ __half g_Ph0[(size_t)N_NODES * D];     // h hi limb, ping
__device__ __half g_Pl0[(size_t)N_NODES * D];     // h lo limb, ping
__device__ __half g_Ph1[(size_t)N_NODES * D];     // pong
__device__ __half g_Pl1[(size_t)N_NODES * D];
__device__ float g_pooled[NUM_GRAPHS * D];
__device__ float g_z1[NUM_GRAPHS * 1024];
__device__ float g_z2[NUM_GRAPHS * 512];
__device__ int   g_idx64;
// CSR
__device__ int g_hist[NPAIR];
__device__ int g_rowptr[NPAIR + 1];
__device__ int g_bsum[NSB];
__device__ int g_boff[NSB];
__device__ int g_esrc[N_EDGES];
// pre-split weights (fp16 hi limb), K-major: [layer][n(256)][k(1792)]
__device__ __half g_Bh[(size_t)N_LAYERS * D * KTOT];
__device__ __half g_Gh[2 * D * D];

// ---------------- PTX helpers (sm_80+ standard) ----------------
__device__ __forceinline__ uint32_t s2u(const void* p) {
    uint32_t a;
    asm("{ .reg .u64 t; cvta.to.shared.u64 t, %1; cvt.u32.u64 %0, t; }" : "=r"(a) : "l"(p));
    return a;
}
__device__ __forceinline__ void ldsm4(uint32_t& r0, uint32_t& r1, uint32_t& r2, uint32_t& r3,
                                      uint32_t addr) {
    asm volatile("ldmatrix.sync.aligned.m8n8.x4.shared.b16 {%0,%1,%2,%3}, [%4];"
                 : "=r"(r0), "=r"(r1), "=r"(r2), "=r"(r3) : "r"(addr));
}
__device__ __forceinline__ void mma16816(float* c, const uint32_t* a, const uint32_t* b) {
    asm volatile(
        "mma.sync.aligned.m16n8k16.row.col.f32.f16.f16.f32 "
        "{%0,%1,%2,%3}, {%4,%5,%6,%7}, {%8,%9}, {%0,%1,%2,%3};"
        : "+f"(c[0]), "+f"(c[1]), "+f"(c[2]), "+f"(c[3])
        : "r"(a[0]), "r"(a[1]), "r"(a[2]), "r"(a[3]), "r"(b[0]), "r"(b[1]));
}
__device__ __forceinline__ void cpasync16(uint32_t saddr, const void* g) {
    asm volatile("cp.async.cg.shared.global [%0], [%1], 16;" :: "r"(saddr), "l"(g));
}
#define CP_COMMIT() asm volatile("cp.async.commit_group;" ::: "memory")
#define CP_WAITG1() asm volatile("cp.async.wait_group 1;" ::: "memory")
#define CP_WAITG0() asm volatile("cp.async.wait_group 0;" ::: "memory")

__device__ __forceinline__ uint32_t packh(__half a, __half b) {
    return ((uint32_t)__half_as_ushort(b) << 16) | __half_as_ushort(a);
}
__device__ __forceinline__ void splith2(float a, float b, uint32_t& hi, uint32_t& lo) {
    __half h0 = __float2half_rn(a), h1 = __float2half_rn(b);
    hi = packh(h0, h1);
    lo = packh(__float2half_rn(a - __half2float(h0)),
               __float2half_rn(b - __half2float(h1)));
}
__device__ __forceinline__ float2 hf22(uint32_t u) {
    __half2 t = *(__half2*)&u;
    return __half22float2(t);
}

// ---------------- index dtype detection ----------------
__global__ void detect_idx_kernel(const void* ei) {
    if (blockIdx.x == 0 && threadIdx.x == 0) {
        const int* p = (const int*)ei;
        int all0 = 1;
        for (int j = 0; j < 64; j++) {
            if (p[2 * j + 1] != 0) { all0 = 0; break; }
        }
        g_idx64 = all0;
    }
}
__device__ __forceinline__ void edge_key(const void* ei, const void* et, int e, int E,
                                         int& s, int& key) {
    if (g_idx64) {
        const long long* p = (const long long*)ei;
        s = (int)p[e];
        key = (int)p[E + e] * N_REL + (int)((const long long*)et)[e];
    } else {
        const int* p = (const int*)ei;
        s = p[e];
        key = p[E + e] * N_REL + ((const int*)et)[e];
    }
}

// ---------------- CSR build ----------------
__global__ void hist_zero_kernel() {
    int i = blockIdx.x * blockDim.x + threadIdx.x;
    if (i < NPAIR) g_hist[i] = 0;
}
__global__ void hist_build_kernel(const void* ei, const void* et, int E) {
    int e = blockIdx.x * blockDim.x + threadIdx.x;
    if (e >= E) return;
    int s, key;
    edge_key(ei, et, e, E, s, key);
    atomicAdd(&g_hist[key], 1);
}
__global__ void scan1_kernel() {
    __shared__ int sh[SCAN_B];
    int tid = threadIdx.x;
    int i = blockIdx.x * SCAN_B + tid;
    int v = (i < NPAIR) ? g_hist[i] : 0;
    sh[tid] = v;
    __syncthreads();
    for (int off = 1; off < SCAN_B; off <<= 1) {
        int t = (tid >= off) ? sh[tid - off] : 0;
        __syncthreads();
        sh[tid] += t;
        __syncthreads();
    }
    if (i < NPAIR) g_rowptr[i + 1] = sh[tid];
    if (tid == SCAN_B - 1) g_bsum[blockIdx.x] = sh[tid];
}
__global__ void scan2_kernel() {
    __shared__ int sh[1024];
    int tid = threadIdx.x;
    int v = (tid < NSB) ? g_bsum[tid] : 0;
    sh[tid] = v;
    __syncthreads();
    for (int off = 1; off < 1024; off <<= 1) {
        int t = (tid >= off) ? sh[tid - off] : 0;
        __syncthreads();
        sh[tid] += t;
        __syncthreads();
    }
    if (tid < NSB) g_boff[tid] = sh[tid] - v;   // exclusive
}
__global__ void scan3_kernel() {
    int i = blockIdx.x * blockDim.x + threadIdx.x;
    if (i >= NPAIR) return;
    int incl = g_rowptr[i + 1] + g_boff[i >> 9];
    g_rowptr[i + 1] = incl;
    g_hist[i] = incl - g_hist[i];               // start position for placement
    if (i == 0) g_rowptr[0] = 0;
}
__global__ void place_kernel(const void* ei, const void* et, int E) {
    int e = blockIdx.x * blockDim.x + threadIdx.x;
    if (e >= E) return;
    int s, key;
    edge_key(ei, et, e, E, s, key);
    int pos = atomicAdd(&g_hist[key], 1);
    g_esrc[pos] = s;
}

// ---------------- per-layer aggregation: A[p] = sum h[src] (hi limb only) --------
// warp per pair; esrc prefetched across lanes and shfl-broadcast to break the
// index->gather dependency chain. Summation order identical to serial loop.
__global__ __launch_bounds__(256) void agg_kernel(const __half* __restrict__ Ph) {
    int p = blockIdx.x * 8 + (threadIdx.x >> 5);
    if (p >= NPAIR) return;
    int lane = threadIdx.x & 31;
    int beg = g_rowptr[p], end = g_rowptr[p + 1];
    int cnt = end - beg;
    float a[8];
#pragma unroll
    for (int j = 0; j < 8; j++) a[j] = 0.f;
    int se = (lane < cnt) ? g_esrc[beg + lane] : 0;   // parallel index prefetch
    int n0 = cnt < 32 ? cnt : 32;
    for (int e = 0; e < n0; e++) {
        int s = __shfl_sync(0xffffffffu, se, e);
        uint4 hv = *(const uint4*)((const char*)Ph + (size_t)s * 512 + (size_t)lane * 16);
        float2 t;
        t = hf22(hv.x); a[0] += t.x; a[1] += t.y;
        t = hf22(hv.y); a[2] += t.x; a[3] += t.y;
        t = hf22(hv.z); a[4] += t.x; a[5] += t.y;
        t = hf22(hv.w); a[6] += t.x; a[7] += t.y;
    }
    for (int e = beg + 32; e < end; e++) {            // rare long-list tail
        int s = g_esrc[e];
        uint4 hv = *(const uint4*)((const char*)Ph + (size_t)s * 512 + (size_t)lane * 16);
        float2 t;
        t = hf22(hv.x); a[0] += t.x; a[1] += t.y;
        t = hf22(hv.y); a[2] += t.x; a[3] += t.y;
        t = hf22(hv.z); a[4] += t.x; a[5] += t.y;
        t = hf22(hv.w); a[6] += t.x; a[7] += t.y;
    }
    uint4 o;
    o.x = packh(__float2half_rn(a[0]), __float2half_rn(a[1]));
    o.y = packh(__float2half_rn(a[2]), __float2half_rn(a[3]));
    o.z = packh(__float2half_rn(a[4]), __float2half_rn(a[5]));
    o.w = packh(__float2half_rn(a[6]), __float2half_rn(a[7]));
    *(uint4*)((char*)g_Af + (size_t)p * 512 + (size_t)lane * 16) = o;
}

// ---------------- encoder: grid-stride, W column in registers ----------------
__global__ __launch_bounds__(256) void encoder_kernel(const float* __restrict__ x,
                                                      const float* __restrict__ W,
                                                      const float* __restrict__ b,
                                                      __half* __restrict__ Ph,
                                                      __half* __restrict__ Pl) {
    int d = threadIdx.x;
    float w[13];
#pragma unroll
    for (int k = 0; k < 13; k++) w[k] = W[k * D + d];
    float bb = b[d];
    __shared__ float xs[13];
    for (int n = blockIdx.x; n < N_NODES; n += gridDim.x) {
        __syncthreads();
        if (d < 13) xs[d] = x[(size_t)n * 13 + d];
        __syncthreads();
        float acc = bb;
#pragma unroll
        for (int k = 0; k < 13; k++) acc = fmaf(xs[k], w[k], acc);
        __half hi = __float2half_rn(acc);
        size_t o = (size_t)n * D + d;
        Ph[o] = hi;
        Pl[o] = __float2half_rn(acc - __half2float(hi));
    }
}

// ---------------- weight pre-split (hi limb only), smem tile-transposed ----------
__global__ void prep_weights2_kernel(const float* __restrict__ relW,
                                     const float* __restrict__ rootW) {
    __shared__ float tile[32][33];
    int layer = blockIdx.z;
    int k0 = blockIdx.x * 32, n0 = blockIdx.y * 32;
    int tx = threadIdx.x, ty = threadIdx.y;
    const float* src = (k0 < KREL)
        ? relW + ((size_t)layer * KREL + k0) * D + n0
        : rootW + ((size_t)layer * D + (k0 - KREL)) * D + n0;
#pragma unroll
    for (int i = 0; i < 32; i += 8)
        tile[ty + i][tx] = src[(size_t)(ty + i) * D + tx];
    __syncthreads();
    size_t base = ((size_t)layer * D + n0) * KTOT + (size_t)k0;
#pragma unroll
    for (int i = 0; i < 32; i += 8) {
        int n = ty + i;
        g_Bh[base + (size_t)n * KTOT + tx] = __float2half_rn(tile[tx][n]);
    }
}
__global__ void prep_g_kernel(const float* __restrict__ gw1,
                              const float* __restrict__ gw2) {
    long u = (long)blockIdx.x * blockDim.x + threadIdx.x;
    if (u >= 2L * D * D) return;
    int w = (int)(u / (D * D));
    int rr = (int)(u % (D * D));
    int n = rr / D, k = rr % D;
    const float* W = w ? gw2 : gw1;
    g_Gh[u] = __float2half_rn(W[k * D + n]);
}

// ---------------- generic zero ----------------
__global__ void zero_kernel(float4* p, long n4) {
    long i = (long)blockIdx.x * blockDim.x + threadIdx.x;
    if (i < n4) p[i] = make_float4(0.f, 0.f, 0.f, 0.f);
}

// ---------------- mma.sync fp16 single-pass GEMM, k64 super-chunks, 3-stage -------
// WM warps in M (x4 in N), warp tile 32x64, NT = WM*128 threads. One sync/chunk.
// EPI 0: v = C + bias + hold(2-limb); prelu; row-l2norm -> 2-limb planes
// EPI 1: v = relu(C + bias) -> 2-limb planes
// EPI 2: v = C + bias -> atomicAdd pooled[batch[row]]  (fused global_add_pool)
template <int EPI, int WM>
__global__ __launch_bounds__(WM * 128, 1) void mgemm_kernel(
    const __half* __restrict__ A1, int lda1, int splitK,
    const __half* __restrict__ A2, int lda2,
    const __half* __restrict__ Bhp, int Kb,
    int M, int K, int Moff,
    const float* __restrict__ bias,
    const float* __restrict__ prelu_a,
    const __half* __restrict__ HoldH, const __half* __restrict__ HoldL,
    __half* __restrict__ CoutH,
    __half* __restrict__ CoutL,
    const void* __restrict__ bat,
    float* __restrict__ pooled) {
    constexpr int NT = WM * 128;
    constexpr int TM = WM * 32;
    constexpr int A_STG = TM * 128;           // TM rows x 128B (k64, single limb)
    constexpr int STG_SZ = A_STG + 32768;     // + B: 256 rows x 128B (k64, 1 limb)
    extern __shared__ char smem[];
    const uint32_t sb = s2u(smem);
    const int tid = threadIdx.x;
    const int wid = tid >> 5, lane = tid & 31;
    const int warpM = wid >> 2, warpN = wid & 3;
    const int m0 = Moff + blockIdx.x * TM;

    float acc[2][8][4];
#pragma unroll
    for (int m = 0; m < 2; m++)
#pragma unroll
        for (int n = 0; n < 8; n++)
#pragma unroll
            for (int j = 0; j < 4; j++) acc[m][n][j] = 0.f;

    const int nsup = K >> 6;

    // ---- A (single limb) -> smem: TM rows x 128B, 4 threads/row, 2 slots each ----
    auto ldA = [&](int t, int s) {
        int kc = t << 6;
        const __half* Ap; int la, kk;
        if (kc < splitK) { Ap = A1; la = lda1; kk = kc; }
        else             { Ap = A2; la = lda2; kk = kc - splitK; }
        int r = tid >> 2, q = tid & 3;
        int grow = m0 + r; if (grow > M - 1) grow = M - 1;
        const char* src = (const char*)Ap + ((size_t)grow * la + kk) * 2 + q * 32;
        uint32_t sw = (uint32_t)(r & 7);
        uint32_t dst = sb + (uint32_t)s * STG_SZ + (uint32_t)r * 128;
        cpasync16(dst + ((((uint32_t)(2 * q)) ^ sw) * 16), src);
        cpasync16(dst + ((((uint32_t)(2 * q + 1)) ^ sw) * 16), src + 16);
    };
    // ---- B (single limb) -> smem: 256 rows x 128B = 2048 16B-chunks ----
    auto ldB = [&](int t, int s) {
        int kc = t << 6;
        uint32_t bbase = sb + (uint32_t)s * STG_SZ + (uint32_t)A_STG;
        for (int idx = tid; idx < 2048; idx += NT) {
            int row = idx >> 3, j = idx & 7;
            const char* src = (const char*)Bhp + ((size_t)row * Kb + kc) * 2 + j * 16;
            uint32_t sw = (uint32_t)(row & 7);
            cpasync16(bbase + (uint32_t)row * 128 + ((((uint32_t)j) ^ sw) * 16), src);
        }
    };
    // ---- single-pass mma over one k64 super-chunk ----
    auto domma = [&](int s) {
        uint32_t abase = sb + (uint32_t)s * STG_SZ;
        uint32_t bbase = abase + (uint32_t)A_STG;
        int arow_l = lane & 15, asel = lane >> 4;
        int brow_l = ((lane >> 4) << 3) + (lane & 7);
        int bsel = (lane >> 3) & 1;
#pragma unroll
        for (int ks = 0; ks < 4; ks++) {   // four k16 steps in k64
            uint32_t Af[2][4];
#pragma unroll
            for (int m = 0; m < 2; m++) {
                int row = warpM * 32 + m * 16 + arow_l;
                uint32_t sw7 = (uint32_t)(row & 7);
                ldsm4(Af[m][0], Af[m][1], Af[m][2], Af[m][3],
                      abase + (uint32_t)row * 128 +
                          ((((uint32_t)(2 * ks + asel)) ^ sw7) * 16));
            }
#pragma unroll
            for (int nb = 0; nb < 4; nb++) {
                int row = warpN * 64 + nb * 16 + brow_l;
                uint32_t sw7 = (uint32_t)(row & 7);
                uint32_t bh_[4];
                ldsm4(bh_[0], bh_[1], bh_[2], bh_[3],
                      bbase + (uint32_t)row * 128 +
                          ((((uint32_t)(2 * ks + bsel)) ^ sw7) * 16));
#pragma unroll
                for (int m = 0; m < 2; m++) {
#pragma unroll
                    for (int j = 0; j < 2; j++)
                        mma16816(acc[m][nb * 2 + j], Af[m], bh_ + 2 * j);
                }
            }
        }
    };

    // ---- 3-stage pipelined main loop, one sync per super-chunk ----
    ldA(0, 0); ldB(0, 0); CP_COMMIT();
    if (nsup > 1) { ldA(1, 1); ldB(1, 1); CP_COMMIT(); }
    for (int t = 0; t < nsup; t++) {
        if (t + 1 < nsup) CP_WAITG1();
        else              CP_WAITG0();
        __syncthreads();      // chunk t visible; domma(t-1) readers done
        if (t + 2 < nsup) { ldA(t + 2, (t + 2) % 3); ldB(t + 2, (t + 2) % 3); CP_COMMIT(); }
        domma(t % 3);
    }

    // ---- fused epilogue ----
    int tq = lane >> 2, tr = lane & 3;
    if (EPI == 0) {
        float aP = prelu_a[0];
        float ssA[2][2];
#pragma unroll
        for (int m = 0; m < 2; m++) {
            int rloc0 = warpM * 32 + m * 16 + tq;
            int row0 = m0 + rloc0, row1 = row0 + 8;
            float s0 = 0.f, s1 = 0.f;
#pragma unroll
            for (int nf = 0; nf < 8; nf++) {
                int col = warpN * 64 + nf * 8 + tr * 2;
                float b0 = bias[col], b1 = bias[col + 1];
                float* C = acc[m][nf];
                if (row0 < M) {
                    size_t o = (size_t)row0 * D + col;
                    float2 hh = hf22(*(const uint32_t*)((const char*)HoldH + o * 2));
                    float2 ll = hf22(*(const uint32_t*)((const char*)HoldL + o * 2));
                    float v0 = C[0] + b0 + hh.x + ll.x; v0 = v0 > 0.f ? v0 : aP * v0;
                    float v1 = C[1] + b1 + hh.y + ll.y; v1 = v1 > 0.f ? v1 : aP * v1;
                    C[0] = v0; C[1] = v1; s0 += v0 * v0 + v1 * v1;
                }
                if (row1 < M) {
                    size_t o = (size_t)row1 * D + col;
                    float2 hh = hf22(*(const uint32_t*)((const char*)HoldH + o * 2));
                    float2 ll = hf22(*(const uint32_t*)((const char*)HoldL + o * 2));
                    float v2 = C[2] + b0 + hh.x + ll.x; v2 = v2 > 0.f ? v2 : aP * v2;
                    float v3 = C[3] + b1 + hh.y + ll.y; v3 = v3 > 0.f ? v3 : aP * v3;
                    C[2] = v2; C[3] = v3; s1 += v2 * v2 + v3 * v3;
                }
            }
            s0 += __shfl_xor_sync(0xffffffffu, s0, 1);
            s0 += __shfl_xor_sync(0xffffffffu, s0, 2);
            s1 += __shfl_xor_sync(0xffffffffu, s1, 1);
            s1 += __shfl_xor_sync(0xffffffffu, s1, 2);
            ssA[m][0] = s0; ssA[m][1] = s1;
        }
        __syncthreads();
        float* rsum = (float*)smem;     // overlay [TM][4]
        if (tr == 0) {
#pragma unroll
            for (int m = 0; m < 2; m++) {
                int rloc0 = warpM * 32 + m * 16 + tq;
                rsum[rloc0 * 4 + warpN] = ssA[m][0];
                rsum[(rloc0 + 8) * 4 + warpN] = ssA[m][1];
            }
        }
        __syncthreads();
#pragma unroll
        for (int m = 0; m < 2; m++) {
            int rloc0 = warpM * 32 + m * 16 + tq;
            float t0 = rsum[rloc0 * 4 + 0] + rsum[rloc0 * 4 + 1] +
                       rsum[rloc0 * 4 + 2] + rsum[rloc0 * 4 + 3];
            float t1 = rsum[(rloc0 + 8) * 4 + 0] + rsum[(rloc0 + 8) * 4 + 1] +
                       rsum[(rloc0 + 8) * 4 + 2] + rsum[(rloc0 + 8) * 4 + 3];
            float inv0 = 1.f / fmaxf(sqrtf(t0), 1e-12f);
            float inv1 = 1.f / fmaxf(sqrtf(t1), 1e-12f);
            int row0 = m0 + rloc0, row1 = row0 + 8;
#pragma unroll
            for (int nf = 0; nf < 8; nf++) {
                int col = warpN * 64 + nf * 8 + tr * 2;
                float* C = acc[m][nf];
                if (row0 < M) {
                    float n0 = C[0] * inv0, n1 = C[1] * inv0;
                    size_t o = (size_t)row0 * D + col;
                    uint32_t hh, ll;
                    splith2(n0, n1, hh, ll);
                    *(uint32_t*)((char*)CoutH + o * 2) = hh;
                    *(uint32_t*)((char*)CoutL + o * 2) = ll;
                }
                if (row1 < M) {
                    float n2 = C[2] * inv1, n3 = C[3] * inv1;
                    size_t o = (size_t)row1 * D + col;
                    uint32_t hh, ll;
                    splith2(n2, n3, hh, ll);
                    *(uint32_t*)((char*)CoutH + o * 2) = hh;
                    *(uint32_t*)((char*)CoutL + o * 2) = ll;
                }
            }
        }
    } else if (EPI == 1) {
#pragma unroll
        for (int m = 0; m < 2; m++) {
            int rloc0 = warpM * 32 + m * 16 + tq;
            int row0 = m0 + rloc0, row1 = row0 + 8;
#pragma unroll
            for (int nf = 0; nf < 8; nf++) {
                int col = warpN * 64 + nf * 8 + tr * 2;
                float b0 = bias[col], b1 = bias[col + 1];
                float* C = acc[m][nf];
                if (row0 < M) {
                    float v0 = fmaxf(C[0] + b0, 0.f), v1 = fmaxf(C[1] + b1, 0.f);
                    size_t o = (size_t)row0 * D + col;
                    uint32_t hh, ll;
                    splith2(v0, v1, hh, ll);
                    *(uint32_t*)((char*)CoutH + o * 2) = hh;
                    *(uint32_t*)((char*)CoutL + o * 2) = ll;
                }
                if (row1 < M) {
                    float v2 = fmaxf(C[2] + b0, 0.f), v3 = fmaxf(C[3] + b1, 0.f);
                    size_t o = (size_t)row1 * D + col;
                    uint32_t hh, ll;
                    splith2(v2, v3, hh, ll);
                    *(uint32_t*)((char*)CoutH + o * 2) = hh;
                    *(uint32_t*)((char*)CoutL + o * 2) = ll;
                }
            }
        }
    } else {   // EPI == 2: fused global_add_pool
#pragma unroll
        for (int m = 0; m < 2; m++) {
            int rloc0 = warpM * 32 + m * 16 + tq;
            int row0 = m0 + rloc0, row1 = row0 + 8;
            int b0g = 0, b1g = 0;
            if (row0 < M)
                b0g = g_idx64 ? (int)((const long long*)bat)[row0] : ((const int*)bat)[row0];
            if (row1 < M)
                b1g = g_idx64 ? (int)((const long long*)bat)[row1] : ((const int*)bat)[row1];
#pragma unroll
            for (int nf = 0; nf < 8; nf++) {
                int col = warpN * 64 + nf * 8 + tr * 2;
                float bb0 = bias[col], bb1 = bias[col + 1];
                float* C = acc[m][nf];
                if (row0 < M) {
                    atomicAdd(pooled + (size_t)b0g * D + col,     C[0] + bb0);
                    atomicAdd(pooled + (size_t)b0g * D + col + 1, C[1] + bb1);
                }
                if (row1 < M) {
                    atomicAdd(pooled + (size_t)b1g * D + col,     C[2] + bb0);
                    atomicAdd(pooled + (size_t)b1g * D + col + 1, C[3] + bb1);
                }
            }
        }
    }
}

#define TS4 (3 * (128 * 128 + 32768))   /* 147456 */
#define TS3 (3 * (96 * 128 + 32768))    /* 135168 */

// ---------------- fp32 SIMT GEMM (small fc layers only) ----------------
#define BM 128
#define BN 128
#define BKK 16
template <int ACT>
__global__ __launch_bounds__(256) void gemm_kernel(
    const float* __restrict__ A, int lda,
    const float* __restrict__ B,
    float* __restrict__ C, int M, int N, int K,
    const float* __restrict__ bias) {
    __shared__ float As[BKK][BM + 1];
    __shared__ float Bs[BKK][BN];
    int tid = threadIdx.x;
    int m0 = blockIdx.y * BM;
    int n0 = blockIdx.x * BN;
    int tm = (tid / 16) * 8;
    int tn = (tid % 16) * 8;
    float acc[8][8];
#pragma unroll
    for (int i = 0; i < 8; i++)
#pragma unroll
        for (int j = 0; j < 8; j++) acc[i][j] = 0.f;
    for (int kt = 0; kt < K; kt += BKK) {
#pragma unroll
        for (int f = tid; f < (BM * BKK / 4); f += 256) {
            int row = f >> 2;
            int c4 = (f & 3) * 4;
            float4 v = make_float4(0.f, 0.f, 0.f, 0.f);
            int grow = m0 + row;
            if (grow < M) v = *(const float4*)(A + (long)grow * lda + kt + c4);
            As[c4 + 0][row] = v.x; As[c4 + 1][row] = v.y;
            As[c4 + 2][row] = v.z; As[c4 + 3][row] = v.w;
        }
#pragma unroll
        for (int f = tid; f < (BKK * BN / 4); f += 256) {
            int kr = f >> 5;
            int c4 = (f & 31) * 4;
            *(float4*)&Bs[kr][c4] = *(const float4*)(B + (long)(kt + kr) * N + n0 + c4);
        }
        __syncthreads();
#pragma unroll
        for (int k = 0; k < BKK; k++) {
            float a[8], b[8];
#pragma unroll
            for (int i = 0; i < 8; i++) a[i] = As[k][tm + i];
#pragma unroll
            for (int j = 0; j < 8; j++) b[j] = Bs[k][tn + j];
#pragma unroll
            for (int i = 0; i < 8; i++)
#pragma unroll
                for (int j = 0; j < 8; j++) acc[i][j] = fmaf(a[i], b[j], acc[i][j]);
        }
        __syncthreads();
    }
#pragma unroll
    for (int i = 0; i < 8; i++) {
        int grow = m0 + tm + i;
        if (grow >= M) break;
        long base = (long)grow * N + n0 + tn;
#pragma unroll
        for (int j4 = 0; j4 < 8; j4 += 4) {
            float4 v;
            float t0 = acc[i][j4 + 0] + bias[n0 + tn + j4 + 0];
            float t1 = acc[i][j4 + 1] + bias[n0 + tn + j4 + 1];
            float t2 = acc[i][j4 + 2] + bias[n0 + tn + j4 + 2];
            float t3 = acc[i][j4 + 3] + bias[n0 + tn + j4 + 3];
            if (ACT == 1) {
                t0 = fmaxf(t0, 0.f); t1 = fmaxf(t1, 0.f);
                t2 = fmaxf(t2, 0.f); t3 = fmaxf(t3, 0.f);
            }
            v.x = t0; v.y = t1; v.z = t2; v.w = t3;
            *(float4*)(C + base + j4) = v;
        }
    }
}

// ---------------- final GEMV ----------------
__global__ void out_gemv_kernel(const float* __restrict__ z2,
                                const float* __restrict__ w,
                                const float* __restrict__ b,
                                float* __restrict__ out) {
    int g = blockIdx.x * blockDim.x + threadIdx.x;
    int row = g >> 5;
    int lane = g & 31;
    if (row >= NUM_GRAPHS) return;
    float acc = 0.f;
#pragma unroll
    for (int k = lane; k < 512; k += 32) acc = fmaf(z2[(long)row * 512 + k], w[k], acc);
#pragma unroll
    for (int o = 16; o > 0; o >>= 1) acc += __shfl_xor_sync(0xffffffffu, acc, o);
    if (lane == 0) out[row] = fmaxf(acc + b[0], 0.f);
}

// ---------------- host ----------------
extern "C" void kernel_launch(void* const* d_in, const int* in_sizes, int n_in,
                              void* d_out, int out_size) {
    const float* x      = (const float*)d_in[0];
    const void*  ei     = d_in[1];
    const void*  et     = d_in[2];
    const void*  bat    = d_in[3];
    const float* enc_W  = (const float*)d_in[4];
    const float* enc_b  = (const float*)d_in[5];
    const float* prelua = (const float*)d_in[6];
    const float* rel_W  = (const float*)d_in[7];
    const float* root_W = (const float*)d_in[8];
    const float* conv_b = (const float*)d_in[9];
    const float* gp_W1  = (const float*)d_in[10];
    const float* gp_b1  = (const float*)d_in[11];
    const float* gp_W2  = (const float*)d_in[12];
    const float* gp_b2  = (const float*)d_in[13];
    const float* fc_W1  = (const float*)d_in[14];
    const float* fc_b1  = (const float*)d_in[15];
    const float* fc_W2  = (const float*)d_in[16];
    const float* fc_b2  = (const float*)d_in[17];
    const float* out_W  = (const float*)d_in[18];
    const float* out_b  = (const float*)d_in[19];
    float* out = (float*)d_out;

    float *P, *Z1, *Z2;
    __half *Af, *Bh, *Gh, *Ph0, *Pl0, *Ph1, *Pl1;
    cudaGetSymbolAddress((void**)&Af, g_Af);
    cudaGetSymbolAddress((void**)&P, g_pooled);
    cudaGetSymbolAddress((void**)&Z1, g_z1);
    cudaGetSymbolAddress((void**)&Z2, g_z2);
    cudaGetSymbolAddress((void**)&Bh, g_Bh);
    cudaGetSymbolAddress((void**)&Gh, g_Gh);
    cudaGetSymbolAddress((void**)&Ph0, g_Ph0);
    cudaGetSymbolAddress((void**)&Pl0, g_Pl0);
    cudaGetSymbolAddress((void**)&Ph1, g_Ph1);
    cudaGetSymbolAddress((void**)&Pl1, g_Pl1);

    cudaFuncSetAttribute(mgemm_kernel<0, 4>, cudaFuncAttributeMaxDynamicSharedMemorySize, TS4);
    cudaFuncSetAttribute(mgemm_kernel<1, 4>, cudaFuncAttributeMaxDynamicSharedMemorySize, TS4);
    cudaFuncSetAttribute(mgemm_kernel<2, 4>, cudaFuncAttributeMaxDynamicSharedMemorySize, TS4);
    cudaFuncSetAttribute(mgemm_kernel<0, 3>, cudaFuncAttributeMaxDynamicSharedMemorySize, TS3);
    cudaFuncSetAttribute(mgemm_kernel<1, 3>, cudaFuncAttributeMaxDynamicSharedMemorySize, TS3);
    cudaFuncSetAttribute(mgemm_kernel<2, 3>, cudaFuncAttributeMaxDynamicSharedMemorySize, TS3);

    detect_idx_kernel<<<1, 32>>>(ei);
    prep_weights2_kernel<<<dim3(KTOT / 32, D / 32, N_LAYERS), dim3(32, 8)>>>(rel_W, root_W);
    prep_g_kernel<<<(2 * D * D + 255) / 256, 256>>>(gp_W1, gp_W2);
    encoder_kernel<<<2960, 256>>>(x, enc_W, enc_b, Ph0, Pl0);

    // CSR build (edge structure is loop-invariant)
    hist_zero_kernel<<<(NPAIR + 255) / 256, 256>>>();
    hist_build_kernel<<<(N_EDGES + 255) / 256, 256>>>(ei, et, N_EDGES);
    scan1_kernel<<<NSB, SCAN_B>>>();
    scan2_kernel<<<1, 1024>>>();
    scan3_kernel<<<(NPAIR + 255) / 256, 256>>>();
    place_kernel<<<(N_EDGES + 255) / 256, 256>>>(ei, et, N_EDGES);

    const int agg_blocks = (NPAIR + 7) / 8;

    __half *PhI = Ph0, *PlI = Pl0, *PhO = Ph1, *PlO = Pl1;
    for (int i = 0; i < N_LAYERS; i++) {
        const __half* Bhi = Bh + (size_t)i * D * KTOT;
        const float* cbi = conv_b + (size_t)i * D;
        agg_kernel<<<agg_blocks, 256>>>(PhI);
        mgemm_kernel<0, 4><<<TILES4, 512, TS4>>>(
            Af, KREL, KREL, PhI, D, Bhi, KTOT,
            N_NODES, KTOT, 0, cbi, prelua, PhI, PlI, PhO, PlO, nullptr, nullptr);
        mgemm_kernel<0, 3><<<TILES3, 384, TS3>>>(
            Af, KREL, KREL, PhI, D, Bhi, KTOT,
            N_NODES, KTOT, OFF4, cbi, prelua, PhI, PlI, PhO, PlO, nullptr, nullptr);
        __half* tb;
        tb = PhI; PhI = PhO; PhO = tb;
        tb = PlI; PlI = PlO; PlO = tb;
    }
    // PhI/PlI = final h planes

    // g = relu(h @ gp_W1 + gp_b1) @ gp_W2 + gp_b2; pool fused into gp2 epilogue
    mgemm_kernel<1, 4><<<TILES4, 512, TS4>>>(
        PhI, D, D, PhI, D, Gh, D,
        N_NODES, D, 0, gp_b1, nullptr, nullptr, nullptr, PhO, PlO, nullptr, nullptr);
    mgemm_kernel<1, 3><<<TILES3, 384, TS3>>>(
        PhI, D, D, PhI, D, Gh, D,
        N_NODES, D, OFF4, gp_b1, nullptr, nullptr, nullptr, PhO, PlO, nullptr, nullptr);
    zero_kernel<<<(NUM_GRAPHS * D / 4 + 255) / 256, 256>>>((float4*)P, NUM_GRAPHS * D / 4);
    mgemm_kernel<2, 4><<<TILES4, 512, TS4>>>(
        PhO, D, D, PhO, D, Gh + (size_t)D * D, D,
        N_NODES, D, 0, gp_b2, nullptr, nullptr, nullptr, nullptr, nullptr, bat, P);
    mgemm_kernel<2, 3><<<TILES3, 384, TS3>>>(
        PhO, D, D, PhO, D, Gh + (size_t)D * D, D,
        N_NODES, D, OFF4, gp_b2, nullptr, nullptr, nullptr, nullptr, nullptr, bat, P);

    // fc stack (tiny — fp32 SIMT)
    gemm_kernel<1><<<dim3(1024 / BN, NUM_GRAPHS / BM), 256>>>(
        P, D, fc_W1, Z1, NUM_GRAPHS, 1024, D, fc_b1);
    gemm_kernel<1><<<dim3(512 / BN, NUM_GRAPHS / BM), 256>>>(
        Z1, 1024, fc_W2, Z2, NUM_GRAPHS, 512, 1024, fc_b2);
    out_gemv_kernel<<<(NUM_GRAPHS * 32 + 255) / 256, 256>>>(Z2, out_W, out_b, out);

    (void)in_sizes; (void)n_in; (void)out_size;
}

// round 16
// speedup vs baseline: 1.1532x; 1.1532x over previous
#include <cuda_runtime.h>
#include <cuda_fp16.h>
#include <cstdint>

#define N_NODES 50000
#define N_EDGES 800000
#define N_REL 6
#define N_LAYERS 8
#define D 256
#define NUM_GRAPHS 512
#define KREL 1536
#define KTOT 1792
#define NPAIR (N_NODES * N_REL)        /* 300000 */
#define SCAN_B 512
#define NSB ((NPAIR + SCAN_B - 1) / SCAN_B)   /* 586 */

// M-split: 296 CTAs x 128 rows (2 exact waves) + 127 CTAs x 96 rows (1 partial wave)
#define TILES4 296
#define OFF4   (TILES4 * 128)   /* 37888 */
#define TILES3 127

// ---------------- scratch (static __device__ — no allocations) ----------------
__device__ __half g_Af[(size_t)N_NODES * KREL];   // aggregated A, single fp16 limb
__device__ __half g_Ph0[(size_t)N_NODES * D];     // h (fp16), ping
__device__ __half g_Ph1[(size_t)N_NODES * D];     // pong
__device__ float g_pooled[NUM_GRAPHS * D];
__device__ float g_z1[NUM_GRAPHS * 1024];
__device__ float g_z2[NUM_GRAPHS * 512];
__device__ int   g_idx64;
// CSR
__device__ int g_hist[NPAIR];
__device__ int g_rowptr[NPAIR + 1];
__device__ int g_bsum[NSB];
__device__ int g_boff[NSB];
__device__ int g_esrc[N_EDGES];
// pre-split weights (fp16 hi limb), K-major: [layer][n(256)][k(1792)]
__device__ __half g_Bh[(size_t)N_LAYERS * D * KTOT];
__device__ __half g_Gh[2 * D * D];

// ---------------- PTX helpers (sm_80+ standard) ----------------
__device__ __forceinline__ uint32_t s2u(const void* p) {
    uint32_t a;
    asm("{ .reg .u64 t; cvta.to.shared.u64 t, %1; cvt.u32.u64 %0, t; }" : "=r"(a) : "l"(p));
    return a;
}
__device__ __forceinline__ void ldsm4(uint32_t& r0, uint32_t& r1, uint32_t& r2, uint32_t& r3,
                                      uint32_t addr) {
    asm volatile("ldmatrix.sync.aligned.m8n8.x4.shared.b16 {%0,%1,%2,%3}, [%4];"
                 : "=r"(r0), "=r"(r1), "=r"(r2), "=r"(r3) : "r"(addr));
}
__device__ __forceinline__ void mma16816(float* c, const uint32_t* a, const uint32_t* b) {
    asm volatile(
        "mma.sync.aligned.m16n8k16.row.col.f32.f16.f16.f32 "
        "{%0,%1,%2,%3}, {%4,%5,%6,%7}, {%8,%9}, {%0,%1,%2,%3};"
        : "+f"(c[0]), "+f"(c[1]), "+f"(c[2]), "+f"(c[3])
        : "r"(a[0]), "r"(a[1]), "r"(a[2]), "r"(a[3]), "r"(b[0]), "r"(b[1]));
}
__device__ __forceinline__ void cpasync16(uint32_t saddr, const void* g) {
    asm volatile("cp.async.cg.shared.global [%0], [%1], 16;" :: "r"(saddr), "l"(g));
}
#define CP_COMMIT() asm volatile("cp.async.commit_group;" ::: "memory")
#define CP_WAITG1() asm volatile("cp.async.wait_group 1;" ::: "memory")
#define CP_WAITG0() asm volatile("cp.async.wait_group 0;" ::: "memory")

__device__ __forceinline__ uint32_t packh(__half a, __half b) {
    return ((uint32_t)__half_as_ushort(b) << 16) | __half_as_ushort(a);
}
__device__ __forceinline__ float2 hf22(uint32_t u) {
    __half2 t = *(__half2*)&u;
    return __half22float2(t);
}

// ---------------- index dtype detection ----------------
__global__ void detect_idx_kernel(const void* ei) {
    if (blockIdx.x == 0 && threadIdx.x == 0) {
        const int* p = (const int*)ei;
        int all0 = 1;
        for (int j = 0; j < 64; j++) {
            if (p[2 * j + 1] != 0) { all0 = 0; break; }
        }
        g_idx64 = all0;
    }
}
__device__ __forceinline__ void edge_key(const void* ei, const void* et, int e, int E,
                                         int& s, int& key) {
    if (g_idx64) {
        const long long* p = (const long long*)ei;
        s = (int)p[e];
        key = (int)p[E + e] * N_REL + (int)((const long long*)et)[e];
    } else {
        const int* p = (const int*)ei;
        s = p[e];
        key = p[E + e] * N_REL + ((const int*)et)[e];
    }
}

// ---------------- CSR build ----------------
__global__ void hist_zero_kernel() {
    int i = blockIdx.x * blockDim.x + threadIdx.x;
    if (i < NPAIR) g_hist[i] = 0;
}
__global__ void hist_build_kernel(const void* ei, const void* et, int E) {
    int e = blockIdx.x * blockDim.x + threadIdx.x;
    if (e >= E) return;
    int s, key;
    edge_key(ei, et, e, E, s, key);
    atomicAdd(&g_hist[key], 1);
}
__global__ void scan1_kernel() {
    __shared__ int sh[SCAN_B];
    int tid = threadIdx.x;
    int i = blockIdx.x * SCAN_B + tid;
    int v = (i < NPAIR) ? g_hist[i] : 0;
    sh[tid] = v;
    __syncthreads();
    for (int off = 1; off < SCAN_B; off <<= 1) {
        int t = (tid >= off) ? sh[tid - off] : 0;
        __syncthreads();
        sh[tid] += t;
        __syncthreads();
    }
    if (i < NPAIR) g_rowptr[i + 1] = sh[tid];
    if (tid == SCAN_B - 1) g_bsum[blockIdx.x] = sh[tid];
}
__global__ void scan2_kernel() {
    __shared__ int sh[1024];
    int tid = threadIdx.x;
    int v = (tid < NSB) ? g_bsum[tid] : 0;
    sh[tid] = v;
    __syncthreads();
    for (int off = 1; off < 1024; off <<= 1) {
        int t = (tid >= off) ? sh[tid - off] : 0;
        __syncthreads();
        sh[tid] += t;
        __syncthreads();
    }
    if (tid < NSB) g_boff[tid] = sh[tid] - v;   // exclusive
}
__global__ void scan3_kernel() {
    int i = blockIdx.x * blockDim.x + threadIdx.x;
    if (i >= NPAIR) return;
    int incl = g_rowptr[i + 1] + g_boff[i >> 9];
    g_rowptr[i + 1] = incl;
    g_hist[i] = incl - g_hist[i];               // start position for placement
    if (i == 0) g_rowptr[0] = 0;
}
__global__ void place_kernel(const void* ei, const void* et, int E) {
    int e = blockIdx.x * blockDim.x + threadIdx.x;
    if (e >= E) return;
    int s, key;
    edge_key(ei, et, e, E, s, key);
    int pos = atomicAdd(&g_hist[key], 1);
    g_esrc[pos] = s;
}

// ---------------- per-layer aggregation: A[p] = sum h[src] (fp16) ----------------
__global__ __launch_bounds__(256) void agg_kernel(const __half* __restrict__ Ph) {
    int p = blockIdx.x * 8 + (threadIdx.x >> 5);
    if (p >= NPAIR) return;
    int lane = threadIdx.x & 31;
    int beg = g_rowptr[p], end = g_rowptr[p + 1];
    float a[8];
#pragma unroll
    for (int j = 0; j < 8; j++) a[j] = 0.f;
    for (int e = beg; e < end; e++) {
        size_t rb = (size_t)g_esrc[e] * 512 + (size_t)lane * 16;
        uint4 hv = *(const uint4*)((const char*)Ph + rb);
        float2 t;
        t = hf22(hv.x); a[0] += t.x; a[1] += t.y;
        t = hf22(hv.y); a[2] += t.x; a[3] += t.y;
        t = hf22(hv.z); a[4] += t.x; a[5] += t.y;
        t = hf22(hv.w); a[6] += t.x; a[7] += t.y;
    }
    uint4 o;
    o.x = packh(__float2half_rn(a[0]), __float2half_rn(a[1]));
    o.y = packh(__float2half_rn(a[2]), __float2half_rn(a[3]));
    o.z = packh(__float2half_rn(a[4]), __float2half_rn(a[5]));
    o.w = packh(__float2half_rn(a[6]), __float2half_rn(a[7]));
    *(uint4*)((char*)g_Af + (size_t)p * 512 + (size_t)lane * 16) = o;
}

// ---------------- encoder: grid-stride, W column in registers ----------------
__global__ __launch_bounds__(256) void encoder_kernel(const float* __restrict__ x,
                                                      const float* __restrict__ W,
                                                      const float* __restrict__ b,
                                                      __half* __restrict__ Ph) {
    int d = threadIdx.x;
    float w[13];
#pragma unroll
    for (int k = 0; k < 13; k++) w[k] = W[k * D + d];
    float bb = b[d];
    __shared__ float xs[13];
    for (int n = blockIdx.x; n < N_NODES; n += gridDim.x) {
        __syncthreads();
        if (d < 13) xs[d] = x[(size_t)n * 13 + d];
        __syncthreads();
        float acc = bb;
#pragma unroll
        for (int k = 0; k < 13; k++) acc = fmaf(xs[k], w[k], acc);
        Ph[(size_t)n * D + d] = __float2half_rn(acc);
    }
}

// ---------------- weight pre-split (hi limb only), smem tile-transposed ----------
__global__ void prep_weights2_kernel(const float* __restrict__ relW,
                                     const float* __restrict__ rootW) {
    __shared__ float tile[32][33];
    int layer = blockIdx.z;
    int k0 = blockIdx.x * 32, n0 = blockIdx.y * 32;
    int tx = threadIdx.x, ty = threadIdx.y;
    const float* src = (k0 < KREL)
        ? relW + ((size_t)layer * KREL + k0) * D + n0
        : rootW + ((size_t)layer * D + (k0 - KREL)) * D + n0;
#pragma unroll
    for (int i = 0; i < 32; i += 8)
        tile[ty + i][tx] = src[(size_t)(ty + i) * D + tx];
    __syncthreads();
    size_t base = ((size_t)layer * D + n0) * KTOT + (size_t)k0;
#pragma unroll
    for (int i = 0; i < 32; i += 8) {
        int n = ty + i;
        g_Bh[base + (size_t)n * KTOT + tx] = __float2half_rn(tile[tx][n]);
    }
}
__global__ void prep_g_kernel(const float* __restrict__ gw1,
                              const float* __restrict__ gw2) {
    long u = (long)blockIdx.x * blockDim.x + threadIdx.x;
    if (u >= 2L * D * D) return;
    int w = (int)(u / (D * D));
    int rr = (int)(u % (D * D));
    int n = rr / D, k = rr % D;
    const float* W = w ? gw2 : gw1;
    g_Gh[u] = __float2half_rn(W[k * D + n]);
}

// ---------------- generic zero ----------------
__global__ void zero_kernel(float4* p, long n4) {
    long i = (long)blockIdx.x * blockDim.x + threadIdx.x;
    if (i < n4) p[i] = make_float4(0.f, 0.f, 0.f, 0.f);
}

// ---------------- mma.sync fp16 single-pass GEMM, k64 super-chunks, 2-stage -------
// WM warps in M (x4 in N), warp tile 32x64, NT = WM*128 threads.
// EPI 0: v = C + bias + hold; prelu; row-l2norm -> Cout (fp16)
// EPI 1: v = relu(C + bias) -> Cout (fp16)
// EPI 2: v = C + bias -> atomicAdd pooled[batch[row]]  (fused global_add_pool)
template <int EPI, int WM>
__global__ __launch_bounds__(WM * 128, 1) void mgemm_kernel(
    const __half* __restrict__ A1, int lda1, int splitK,
    const __half* __restrict__ A2, int lda2,
    const __half* __restrict__ Bhp, int Kb,
    int M, int K, int Moff,
    const float* __restrict__ bias,
    const float* __restrict__ prelu_a,
    const __half* __restrict__ HoldH,
    __half* __restrict__ CoutH,
    const void* __restrict__ bat,
    float* __restrict__ pooled) {
    constexpr int NT = WM * 128;
    constexpr int TM = WM * 32;
    constexpr int A_STG = TM * 128;           // TM rows x 128B (k64, single limb)
    constexpr int STG_SZ = A_STG + 32768;     // + B: 256 rows x 128B (k64, 1 limb)
    extern __shared__ char smem[];
    const uint32_t sb = s2u(smem);
    const int tid = threadIdx.x;
    const int wid = tid >> 5, lane = tid & 31;
    const int warpM = wid >> 2, warpN = wid & 3;
    const int m0 = Moff + blockIdx.x * TM;

    float acc[2][8][4];
#pragma unroll
    for (int m = 0; m < 2; m++)
#pragma unroll
        for (int n = 0; n < 8; n++)
#pragma unroll
            for (int j = 0; j < 4; j++) acc[m][n][j] = 0.f;

    const int nsup = K >> 6;

    // ---- A (single limb) -> smem: TM rows x 128B, 4 threads/row, 2 slots each ----
    auto ldA = [&](int t, int s) {
        int kc = t << 6;
        const __half* Ap; int la, kk;
        if (kc < splitK) { Ap = A1; la = lda1; kk = kc; }
        else             { Ap = A2; la = lda2; kk = kc - splitK; }
        int r = tid >> 2, q = tid & 3;
        int grow = m0 + r; if (grow > M - 1) grow = M - 1;
        const char* src = (const char*)Ap + ((size_t)grow * la + kk) * 2 + q * 32;
        uint32_t sw = (uint32_t)(r & 7);
        uint32_t dst = sb + (uint32_t)s * STG_SZ + (uint32_t)r * 128;
        cpasync16(dst + ((((uint32_t)(2 * q)) ^ sw) * 16), src);
        cpasync16(dst + ((((uint32_t)(2 * q + 1)) ^ sw) * 16), src + 16);
    };
    // ---- B (single limb) -> smem: 256 rows x 128B = 2048 16B-chunks ----
    auto ldB = [&](int t, int s) {
        int kc = t << 6;
        uint32_t bbase = sb + (uint32_t)s * STG_SZ + (uint32_t)A_STG;
        for (int idx = tid; idx < 2048; idx += NT) {
            int row = idx >> 3, j = idx & 7;
            const char* src = (const char*)Bhp + ((size_t)row * Kb + kc) * 2 + j * 16;
            uint32_t sw = (uint32_t)(row & 7);
            cpasync16(bbase + (uint32_t)row * 128 + ((((uint32_t)j) ^ sw) * 16), src);
        }
    };
    // ---- single-pass mma over one k64 super-chunk ----
    auto domma = [&](int s) {
        uint32_t abase = sb + (uint32_t)s * STG_SZ;
        uint32_t bbase = abase + (uint32_t)A_STG;
        int arow_l = lane & 15, asel = lane >> 4;
        int brow_l = ((lane >> 4) << 3) + (lane & 7);
        int bsel = (lane >> 3) & 1;
#pragma unroll
        for (int ks = 0; ks < 4; ks++) {   // four k16 steps in k64
            uint32_t Af[2][4];
#pragma unroll
            for (int m = 0; m < 2; m++) {
                int row = warpM * 32 + m * 16 + arow_l;
                uint32_t sw7 = (uint32_t)(row & 7);
                ldsm4(Af[m][0], Af[m][1], Af[m][2], Af[m][3],
                      abase + (uint32_t)row * 128 +
                          ((((uint32_t)(2 * ks + asel)) ^ sw7) * 16));
            }
#pragma unroll
            for (int nb = 0; nb < 4; nb++) {
                int row = warpN * 64 + nb * 16 + brow_l;
                uint32_t sw7 = (uint32_t)(row & 7);
                uint32_t bh_[4];
                ldsm4(bh_[0], bh_[1], bh_[2], bh_[3],
                      bbase + (uint32_t)row * 128 +
                          ((((uint32_t)(2 * ks + bsel)) ^ sw7) * 16));
#pragma unroll
                for (int m = 0; m < 2; m++) {
#pragma unroll
                    for (int j = 0; j < 2; j++)
                        mma16816(acc[m][nb * 2 + j], Af[m], bh_ + 2 * j);
                }
            }
        }
    };

    // ---- 2-stage pipelined main loop over super-chunks (proven R14 schedule) ----
    ldA(0, 0); ldB(0, 0); CP_COMMIT();
    if (nsup > 1) { ldA(1, 1); ldB(1, 1); }
    CP_COMMIT();
    for (int t = 0; t < nsup; t++) {
        if (t + 1 < nsup) CP_WAITG1();
        else              CP_WAITG0();
        __syncthreads();
        domma(t & 1);
        __syncthreads();
        if (t + 2 < nsup) { ldA(t + 2, t & 1); ldB(t + 2, t & 1); }
        CP_COMMIT();
    }

    // ---- fused epilogue ----
    int tq = lane >> 2, tr = lane & 3;
    if (EPI == 0) {
        float aP = prelu_a[0];
        float ssA[2][2];
#pragma unroll
        for (int m = 0; m < 2; m++) {
            int rloc0 = warpM * 32 + m * 16 + tq;
            int row0 = m0 + rloc0, row1 = row0 + 8;
            float s0 = 0.f, s1 = 0.f;
#pragma unroll
            for (int nf = 0; nf < 8; nf++) {
                int col = warpN * 64 + nf * 8 + tr * 2;
                float b0 = bias[col], b1 = bias[col + 1];
                float* C = acc[m][nf];
                if (row0 < M) {
                    size_t o = (size_t)row0 * D + col;
                    float2 hh = hf22(*(const uint32_t*)((const char*)HoldH + o * 2));
                    float v0 = C[0] + b0 + hh.x; v0 = v0 > 0.f ? v0 : aP * v0;
                    float v1 = C[1] + b1 + hh.y; v1 = v1 > 0.f ? v1 : aP * v1;
                    C[0] = v0; C[1] = v1; s0 += v0 * v0 + v1 * v1;
                }
                if (row1 < M) {
                    size_t o = (size_t)row1 * D + col;
                    float2 hh = hf22(*(const uint32_t*)((const char*)HoldH + o * 2));
                    float v2 = C[2] + b0 + hh.x; v2 = v2 > 0.f ? v2 : aP * v2;
                    float v3 = C[3] + b1 + hh.y; v3 = v3 > 0.f ? v3 : aP * v3;
                    C[2] = v2; C[3] = v3; s1 += v2 * v2 + v3 * v3;
                }
            }
            s0 += __shfl_xor_sync(0xffffffffu, s0, 1);
            s0 += __shfl_xor_sync(0xffffffffu, s0, 2);
            s1 += __shfl_xor_sync(0xffffffffu, s1, 1);
            s1 += __shfl_xor_sync(0xffffffffu, s1, 2);
            ssA[m][0] = s0; ssA[m][1] = s1;
        }
        __syncthreads();
        float* rsum = (float*)smem;     // overlay [TM][4]
        if (tr == 0) {
#pragma unroll
            for (int m = 0; m < 2; m++) {
                int rloc0 = warpM * 32 + m * 16 + tq;
                rsum[rloc0 * 4 + warpN] = ssA[m][0];
                rsum[(rloc0 + 8) * 4 + warpN] = ssA[m][1];
            }
        }
        __syncthreads();
#pragma unroll
        for (int m = 0; m < 2; m++) {
            int rloc0 = warpM * 32 + m * 16 + tq;
            float t0 = rsum[rloc0 * 4 + 0] + rsum[rloc0 * 4 + 1] +
                       rsum[rloc0 * 4 + 2] + rsum[rloc0 * 4 + 3];
            float t1 = rsum[(rloc0 + 8) * 4 + 0] + rsum[(rloc0 + 8) * 4 + 1] +
                       rsum[(rloc0 + 8) * 4 + 2] + rsum[(rloc0 + 8) * 4 + 3];
            float inv0 = 1.f / fmaxf(sqrtf(t0), 1e-12f);
            float inv1 = 1.f / fmaxf(sqrtf(t1), 1e-12f);
            int row0 = m0 + rloc0, row1 = row0 + 8;
#pragma unroll
            for (int nf = 0; nf < 8; nf++) {
                int col = warpN * 64 + nf * 8 + tr * 2;
                float* C = acc[m][nf];
                if (row0 < M) {
                    size_t o = (size_t)row0 * D + col;
                    *(uint32_t*)((char*)CoutH + o * 2) =
                        packh(__float2half_rn(C[0] * inv0), __float2half_rn(C[1] * inv0));
                }
                if (row1 < M) {
                    size_t o = (size_t)row1 * D + col;
                    *(uint32_t*)((char*)CoutH + o * 2) =
                        packh(__float2half_rn(C[2] * inv1), __float2half_rn(C[3] * inv1));
                }
            }
        }
    } else if (EPI == 1) {
#pragma unroll
        for (int m = 0; m < 2; m++) {
            int rloc0 = warpM * 32 + m * 16 + tq;
            int row0 = m0 + rloc0, row1 = row0 + 8;
#pragma unroll
            for (int nf = 0; nf < 8; nf++) {
                int col = warpN * 64 + nf * 8 + tr * 2;
                float b0 = bias[col], b1 = bias[col + 1];
                float* C = acc[m][nf];
                if (row0 < M) {
                    size_t o = (size_t)row0 * D + col;
                    *(uint32_t*)((char*)CoutH + o * 2) =
                        packh(__float2half_rn(fmaxf(C[0] + b0, 0.f)),
                              __float2half_rn(fmaxf(C[1] + b1, 0.f)));
                }
                if (row1 < M) {
                    size_t o = (size_t)row1 * D + col;
                    *(uint32_t*)((char*)CoutH + o * 2) =
                        packh(__float2half_rn(fmaxf(C[2] + b0, 0.f)),
                              __float2half_rn(fmaxf(C[3] + b1, 0.f)));
                }
            }
        }
    } else {   // EPI == 2: fused global_add_pool
#pragma unroll
        for (int m = 0; m < 2; m++) {
            int rloc0 = warpM * 32 + m * 16 + tq;
            int row0 = m0 + rloc0, row1 = row0 + 8;
            int b0g = 0, b1g = 0;
            if (row0 < M)
                b0g = g_idx64 ? (int)((const long long*)bat)[row0] : ((const int*)bat)[row0];
            if (row1 < M)
                b1g = g_idx64 ? (int)((const long long*)bat)[row1] : ((const int*)bat)[row1];
#pragma unroll
            for (int nf = 0; nf < 8; nf++) {
                int col = warpN * 64 + nf * 8 + tr * 2;
                float bb0 = bias[col], bb1 = bias[col + 1];
                float* C = acc[m][nf];
                if (row0 < M) {
                    atomicAdd(pooled + (size_t)b0g * D + col,     C[0] + bb0);
                    atomicAdd(pooled + (size_t)b0g * D + col + 1, C[1] + bb1);
                }
                if (row1 < M) {
                    atomicAdd(pooled + (size_t)b1g * D + col,     C[2] + bb0);
                    atomicAdd(pooled + (size_t)b1g * D + col + 1, C[3] + bb1);
                }
            }
        }
    }
}

#define TS4 (2 * (128 * 128 + 32768))   /* 98304 */
#define TS3 (2 * (96 * 128 + 32768))    /* 90112 */

// ---------------- fp32 SIMT GEMM (small fc layers only) ----------------
#define BM 128
#define BN 128
#define BKK 16
template <int ACT>
__global__ __launch_bounds__(256) void gemm_kernel(
    const float* __restrict__ A, int lda,
    const float* __restrict__ B,
    float* __restrict__ C, int M, int N, int K,
    const float* __restrict__ bias) {
    __shared__ float As[BKK][BM + 1];
    __shared__ float Bs[BKK][BN];
    int tid = threadIdx.x;
    int m0 = blockIdx.y * BM;
    int n0 = blockIdx.x * BN;
    int tm = (tid / 16) * 8;
    int tn = (tid % 16) * 8;
    float acc[8][8];
#pragma unroll
    for (int i = 0; i < 8; i++)
#pragma unroll
        for (int j = 0; j < 8; j++) acc[i][j] = 0.f;
    for (int kt = 0; kt < K; kt += BKK) {
#pragma unroll
        for (int f = tid; f < (BM * BKK / 4); f += 256) {
            int row = f >> 2;
            int c4 = (f & 3) * 4;
            float4 v = make_float4(0.f, 0.f, 0.f, 0.f);
            int grow = m0 + row;
            if (grow < M) v = *(const float4*)(A + (long)grow * lda + kt + c4);
            As[c4 + 0][row] = v.x; As[c4 + 1][row] = v.y;
            As[c4 + 2][row] = v.z; As[c4 + 3][row] = v.w;
        }
#pragma unroll
        for (int f = tid; f < (BKK * BN / 4); f += 256) {
            int kr = f >> 5;
            int c4 = (f & 31) * 4;
            *(float4*)&Bs[kr][c4] = *(const float4*)(B + (long)(kt + kr) * N + n0 + c4);
        }
        __syncthreads();
#pragma unroll
        for (int k = 0; k < BKK; k++) {
            float a[8], b[8];
#pragma unroll
            for (int i = 0; i < 8; i++) a[i] = As[k][tm + i];
#pragma unroll
            for (int j = 0; j < 8; j++) b[j] = Bs[k][tn + j];
#pragma unroll
            for (int i = 0; i < 8; i++)
#pragma unroll
                for (int j = 0; j < 8; j++) acc[i][j] = fmaf(a[i], b[j], acc[i][j]);
        }
        __syncthreads();
    }
#pragma unroll
    for (int i = 0; i < 8; i++) {
        int grow = m0 + tm + i;
        if (grow >= M) break;
        long base = (long)grow * N + n0 + tn;
#pragma unroll
        for (int j4 = 0; j4 < 8; j4 += 4) {
            float4 v;
            float t0 = acc[i][j4 + 0] + bias[n0 + tn + j4 + 0];
            float t1 = acc[i][j4 + 1] + bias[n0 + tn + j4 + 1];
            float t2 = acc[i][j4 + 2] + bias[n0 + tn + j4 + 2];
            float t3 = acc[i][j4 + 3] + bias[n0 + tn + j4 + 3];
            if (ACT == 1) {
                t0 = fmaxf(t0, 0.f); t1 = fmaxf(t1, 0.f);
                t2 = fmaxf(t2, 0.f); t3 = fmaxf(t3, 0.f);
            }
            v.x = t0; v.y = t1; v.z = t2; v.w = t3;
            *(float4*)(C + base + j4) = v;
        }
    }
}

// ---------------- final GEMV ----------------
__global__ void out_gemv_kernel(const float* __restrict__ z2,
                                const float* __restrict__ w,
                                const float* __restrict__ b,
                                float* __restrict__ out) {
    int g = blockIdx.x * blockDim.x + threadIdx.x;
    int row = g >> 5;
    int lane = g & 31;
    if (row >= NUM_GRAPHS) return;
    float acc = 0.f;
#pragma unroll
    for (int k = lane; k < 512; k += 32) acc = fmaf(z2[(long)row * 512 + k], w[k], acc);
#pragma unroll
    for (int o = 16; o > 0; o >>= 1) acc += __shfl_xor_sync(0xffffffffu, acc, o);
    if (lane == 0) out[row] = fmaxf(acc + b[0], 0.f);
}

// ---------------- host ----------------
extern "C" void kernel_launch(void* const* d_in, const int* in_sizes, int n_in,
                              void* d_out, int out_size) {
    const float* x      = (const float*)d_in[0];
    const void*  ei     = d_in[1];
    const void*  et     = d_in[2];
    const void*  bat    = d_in[3];
    const float* enc_W  = (const float*)d_in[4];
    const float* enc_b  = (const float*)d_in[5];
    const float* prelua = (const float*)d_in[6];
    const float* rel_W  = (const float*)d_in[7];
    const float* root_W = (const float*)d_in[8];
    const float* conv_b = (const float*)d_in[9];
    const float* gp_W1  = (const float*)d_in[10];
    const float* gp_b1  = (const float*)d_in[11];
    const float* gp_W2  = (const float*)d_in[12];
    const float* gp_b2  = (const float*)d_in[13];
    const float* fc_W1  = (const float*)d_in[14];
    const float* fc_b1  = (const float*)d_in[15];
    const float* fc_W2  = (const float*)d_in[16];
    const float* fc_b2  = (const float*)d_in[17];
    const float* out_W  = (const float*)d_in[18];
    const float* out_b  = (const float*)d_in[19];
    float* out = (float*)d_out;

    float *P, *Z1, *Z2;
    __half *Af, *Bh, *Gh, *Ph0, *Ph1;
    cudaGetSymbolAddress((void**)&Af, g_Af);
    cudaGetSymbolAddress((void**)&P, g_pooled);
    cudaGetSymbolAddress((void**)&Z1, g_z1);
    cudaGetSymbolAddress((void**)&Z2, g_z2);
    cudaGetSymbolAddress((void**)&Bh, g_Bh);
    cudaGetSymbolAddress((void**)&Gh, g_Gh);
    cudaGetSymbolAddress((void**)&Ph0, g_Ph0);
    cudaGetSymbolAddress((void**)&Ph1, g_Ph1);

    cudaFuncSetAttribute(mgemm_kernel<0, 4>, cudaFuncAttributeMaxDynamicSharedMemorySize, TS4);
    cudaFuncSetAttribute(mgemm_kernel<1, 4>, cudaFuncAttributeMaxDynamicSharedMemorySize, TS4);
    cudaFuncSetAttribute(mgemm_kernel<2, 4>, cudaFuncAttributeMaxDynamicSharedMemorySize, TS4);
    cudaFuncSetAttribute(mgemm_kernel<0, 3>, cudaFuncAttributeMaxDynamicSharedMemorySize, TS3);
    cudaFuncSetAttribute(mgemm_kernel<1, 3>, cudaFuncAttributeMaxDynamicSharedMemorySize, TS3);
    cudaFuncSetAttribute(mgemm_kernel<2, 3>, cudaFuncAttributeMaxDynamicSharedMemorySize, TS3);

    detect_idx_kernel<<<1, 32>>>(ei);
    prep_weights2_kernel<<<dim3(KTOT / 32, D / 32, N_LAYERS), dim3(32, 8)>>>(rel_W, root_W);
    prep_g_kernel<<<(2 * D * D + 255) / 256, 256>>>(gp_W1, gp_W2);
    encoder_kernel<<<2960, 256>>>(x, enc_W, enc_b, Ph0);

    // CSR build (edge structure is loop-invariant)
    hist_zero_kernel<<<(NPAIR + 255) / 256, 256>>>();
    hist_build_kernel<<<(N_EDGES + 255) / 256, 256>>>(ei, et, N_EDGES);
    scan1_kernel<<<NSB, SCAN_B>>>();
    scan2_kernel<<<1, 1024>>>();
    scan3_kernel<<<(NPAIR + 255) / 256, 256>>>();
    place_kernel<<<(N_EDGES + 255) / 256, 256>>>(ei, et, N_EDGES);

    const int agg_blocks = (NPAIR + 7) / 8;

    __half *PhI = Ph0, *PhO = Ph1;
    for (int i = 0; i < N_LAYERS; i++) {
        const __half* Bhi = Bh + (size_t)i * D * KTOT;
        const float* cbi = conv_b + (size_t)i * D;
        agg_kernel<<<agg_blocks, 256>>>(PhI);
        mgemm_kernel<0, 4><<<TILES4, 512, TS4>>>(
            Af, KREL, KREL, PhI, D, Bhi, KTOT,
            N_NODES, KTOT, 0, cbi, prelua, PhI, PhO, nullptr, nullptr);
        mgemm_kernel<0, 3><<<TILES3, 384, TS3>>>(
            Af, KREL, KREL, PhI, D, Bhi, KTOT,
            N_NODES, KTOT, OFF4, cbi, prelua, PhI, PhO, nullptr, nullptr);
        __half* tb = PhI; PhI = PhO; PhO = tb;
    }
    // PhI = final h (fp16)

    // g = relu(h @ gp_W1 + gp_b1) @ gp_W2 + gp_b2; pool fused into gp2 epilogue
    mgemm_kernel<1, 4><<<TILES4, 512, TS4>>>(
        PhI, D, D, PhI, D, Gh, D,
        N_NODES, D, 0, gp_b1, nullptr, nullptr, PhO, nullptr, nullptr);
    mgemm_kernel<1, 3><<<TILES3, 384, TS3>>>(
        PhI, D, D, PhI, D, Gh, D,
        N_NODES, D, OFF4, gp_b1, nullptr, nullptr, PhO, nullptr, nullptr);
    zero_kernel<<<(NUM_GRAPHS * D / 4 + 255) / 256, 256>>>((float4*)P, NUM_GRAPHS * D / 4);
    mgemm_kernel<2, 4><<<TILES4, 512, TS4>>>(
        PhO, D, D, PhO, D, Gh + (size_t)D * D, D,
        N_NODES, D, 0, gp_b2, nullptr, nullptr, nullptr, bat, P);
    mgemm_kernel<2, 3><<<TILES3, 384, TS3>>>(
        PhO, D, D, PhO, D, Gh + (size_t)D * D, D,
        N_NODES, D, OFF4, gp_b2, nullptr, nullptr, nullptr, bat, P);

    // fc stack (tiny — fp32 SIMT)
    gemm_kernel<1><<<dim3(1024 / BN, NUM_GRAPHS / BM), 256>>>(
        P, D, fc_W1, Z1, NUM_GRAPHS, 1024, D, fc_b1);
    gemm_kernel<1><<<dim3(512 / BN, NUM_GRAPHS / BM), 256>>>(
        Z1, 1024, fc_W2, Z2, NUM_GRAPHS, 512, 1024, fc_b2);
    out_gemv_kernel<<<(NUM_GRAPHS * 32 + 255) / 256, 256>>>(Z2, out_W, out_b, out);

    (void)in_sizes; (void)n_in; (void)out_size;
}

// round 17
// speedup vs baseline: 1.1653x; 1.0105x over previous
#include <cuda_runtime.h>
#include <cuda_fp16.h>
#include <cstdint>

#define N_NODES 50000
#define N_EDGES 800000
#define N_REL 6
#define N_LAYERS 8
#define D 256
#define NUM_GRAPHS 512
#define KREL 1536
#define KTOT 1792
#define NPAIR (N_NODES * N_REL)        /* 300000 */
#define SCAN_B 512
#define NSB ((NPAIR + SCAN_B - 1) / SCAN_B)   /* 586 */

// M-split: 296 CTAs x 128 rows (2 exact waves) + 127 CTAs x 96 rows (1 partial wave)
#define TILES4 296
#define OFF4   (TILES4 * 128)   /* 37888 */
#define TILES3 127

// ---------------- scratch (static __device__ — no allocations) ----------------
__device__ __half g_Af[(size_t)N_NODES * KREL];   // aggregated A (fp16)
__device__ __half g_Ph0[(size_t)N_NODES * D];     // h (fp16), ping
__device__ __half g_Ph1[(size_t)N_NODES * D];     // pong
__device__ float g_pooled[NUM_GRAPHS * D];
__device__ float g_z1[NUM_GRAPHS * 1024];
__device__ float g_z2[NUM_GRAPHS * 512];
__device__ int   g_idx64;
// CSR
__device__ int g_hist[NPAIR];
__device__ int g_rowptr[NPAIR + 1];
__device__ int g_bsum[NSB];
__device__ int g_boff[NSB];
__device__ int g_esrc[N_EDGES];
// pre-converted weights (fp16), K-major: [layer][n(256)][k(1792)]
__device__ __half g_Bh[(size_t)N_LAYERS * D * KTOT];
__device__ __half g_Gh[2 * D * D];

// ---------------- PTX helpers (sm_80+ standard) ----------------
__device__ __forceinline__ uint32_t s2u(const void* p) {
    uint32_t a;
    asm("{ .reg .u64 t; cvta.to.shared.u64 t, %1; cvt.u32.u64 %0, t; }" : "=r"(a) : "l"(p));
    return a;
}
__device__ __forceinline__ void ldsm4(uint32_t& r0, uint32_t& r1, uint32_t& r2, uint32_t& r3,
                                      uint32_t addr) {
    asm volatile("ldmatrix.sync.aligned.m8n8.x4.shared.b16 {%0,%1,%2,%3}, [%4];"
                 : "=r"(r0), "=r"(r1), "=r"(r2), "=r"(r3) : "r"(addr));
}
__device__ __forceinline__ void mma16816(float* c, const uint32_t* a, const uint32_t* b) {
    asm volatile(
        "mma.sync.aligned.m16n8k16.row.col.f32.f16.f16.f32 "
        "{%0,%1,%2,%3}, {%4,%5,%6,%7}, {%8,%9}, {%0,%1,%2,%3};"
        : "+f"(c[0]), "+f"(c[1]), "+f"(c[2]), "+f"(c[3])
        : "r"(a[0]), "r"(a[1]), "r"(a[2]), "r"(a[3]), "r"(b[0]), "r"(b[1]));
}
__device__ __forceinline__ void cpasync16(uint32_t saddr, const void* g) {
    asm volatile("cp.async.cg.shared.global [%0], [%1], 16;" :: "r"(saddr), "l"(g));
}
#define CP_COMMIT() asm volatile("cp.async.commit_group;" ::: "memory")
#define CP_WAITG1() asm volatile("cp.async.wait_group 1;" ::: "memory")
#define CP_WAITG0() asm volatile("cp.async.wait_group 0;" ::: "memory")

__device__ __forceinline__ uint32_t packh(__half a, __half b) {
    return ((uint32_t)__half_as_ushort(b) << 16) | __half_as_ushort(a);
}
__device__ __forceinline__ float2 hf22(uint32_t u) {
    __half2 t = *(__half2*)&u;
    return __half22float2(t);
}

// ---------------- index dtype detection ----------------
__global__ void detect_idx_kernel(const void* ei) {
    if (blockIdx.x == 0 && threadIdx.x == 0) {
        const int* p = (const int*)ei;
        int all0 = 1;
        for (int j = 0; j < 64; j++) {
            if (p[2 * j + 1] != 0) { all0 = 0; break; }
        }
        g_idx64 = all0;
    }
}
__device__ __forceinline__ void edge_key(const void* ei, const void* et, int e, int E,
                                         int& s, int& key) {
    if (g_idx64) {
        const long long* p = (const long long*)ei;
        s = (int)p[e];
        key = (int)p[E + e] * N_REL + (int)((const long long*)et)[e];
    } else {
        const int* p = (const int*)ei;
        s = p[e];
        key = p[E + e] * N_REL + ((const int*)et)[e];
    }
}

// ---------------- CSR build ----------------
__global__ void hist_zero_kernel() {
    int i = blockIdx.x * blockDim.x + threadIdx.x;
    if (i < NPAIR) g_hist[i] = 0;
}
__global__ void hist_build_kernel(const void* ei, const void* et, int E) {
    int e = blockIdx.x * blockDim.x + threadIdx.x;
    if (e >= E) return;
    int s, key;
    edge_key(ei, et, e, E, s, key);
    atomicAdd(&g_hist[key], 1);
}
__global__ void scan1_kernel() {
    __shared__ int sh[SCAN_B];
    int tid = threadIdx.x;
    int i = blockIdx.x * SCAN_B + tid;
    int v = (i < NPAIR) ? g_hist[i] : 0;
    sh[tid] = v;
    __syncthreads();
    for (int off = 1; off < SCAN_B; off <<= 1) {
        int t = (tid >= off) ? sh[tid - off] : 0;
        __syncthreads();
        sh[tid] += t;
        __syncthreads();
    }
    if (i < NPAIR) g_rowptr[i + 1] = sh[tid];
    if (tid == SCAN_B - 1) g_bsum[blockIdx.x] = sh[tid];
}
__global__ void scan2_kernel() {
    __shared__ int sh[1024];
    int tid = threadIdx.x;
    int v = (tid < NSB) ? g_bsum[tid] : 0;
    sh[tid] = v;
    __syncthreads();
    for (int off = 1; off < 1024; off <<= 1) {
        int t = (tid >= off) ? sh[tid - off] : 0;
        __syncthreads();
        sh[tid] += t;
        __syncthreads();
    }
    if (tid < NSB) g_boff[tid] = sh[tid] - v;   // exclusive
}
__global__ void scan3_kernel() {
    int i = blockIdx.x * blockDim.x + threadIdx.x;
    if (i >= NPAIR) return;
    int incl = g_rowptr[i + 1] + g_boff[i >> 9];
    g_rowptr[i + 1] = incl;
    g_hist[i] = incl - g_hist[i];               // start position for placement
    if (i == 0) g_rowptr[0] = 0;
}
__global__ void place_kernel(const void* ei, const void* et, int E) {
    int e = blockIdx.x * blockDim.x + threadIdx.x;
    if (e >= E) return;
    int s, key;
    edge_key(ei, et, e, E, s, key);
    int pos = atomicAdd(&g_hist[key], 1);
    g_esrc[pos] = s;
}

// ---------------- per-layer aggregation (2-edge unrolled for MLP) ----------------
__global__ __launch_bounds__(256) void agg_kernel(const __half* __restrict__ Ph) {
    int p = blockIdx.x * 8 + (threadIdx.x >> 5);
    if (p >= NPAIR) return;
    int lane = threadIdx.x & 31;
    int beg = g_rowptr[p], end = g_rowptr[p + 1];
    float a[8];
#pragma unroll
    for (int j = 0; j < 8; j++) a[j] = 0.f;
    int e = beg;
    for (; e + 1 < end; e += 2) {
        size_t r0 = (size_t)g_esrc[e] * 512 + (size_t)lane * 16;
        size_t r1 = (size_t)g_esrc[e + 1] * 512 + (size_t)lane * 16;
        uint4 h0 = *(const uint4*)((const char*)Ph + r0);
        uint4 h1 = *(const uint4*)((const char*)Ph + r1);
        float2 t;
        t = hf22(h0.x); a[0] += t.x; a[1] += t.y;
        t = hf22(h0.y); a[2] += t.x; a[3] += t.y;
        t = hf22(h0.z); a[4] += t.x; a[5] += t.y;
        t = hf22(h0.w); a[6] += t.x; a[7] += t.y;
        t = hf22(h1.x); a[0] += t.x; a[1] += t.y;
        t = hf22(h1.y); a[2] += t.x; a[3] += t.y;
        t = hf22(h1.z); a[4] += t.x; a[5] += t.y;
        t = hf22(h1.w); a[6] += t.x; a[7] += t.y;
    }
    if (e < end) {
        size_t rb = (size_t)g_esrc[e] * 512 + (size_t)lane * 16;
        uint4 hv = *(const uint4*)((const char*)Ph + rb);
        float2 t;
        t = hf22(hv.x); a[0] += t.x; a[1] += t.y;
        t = hf22(hv.y); a[2] += t.x; a[3] += t.y;
        t = hf22(hv.z); a[4] += t.x; a[5] += t.y;
        t = hf22(hv.w); a[6] += t.x; a[7] += t.y;
    }
    uint4 o;
    o.x = packh(__float2half_rn(a[0]), __float2half_rn(a[1]));
    o.y = packh(__float2half_rn(a[2]), __float2half_rn(a[3]));
    o.z = packh(__float2half_rn(a[4]), __float2half_rn(a[5]));
    o.w = packh(__float2half_rn(a[6]), __float2half_rn(a[7]));
    *(uint4*)((char*)g_Af + (size_t)p * 512 + (size_t)lane * 16) = o;
}

// ---------------- encoder: grid-stride, 2 nodes/iter, W column in registers ------
__global__ __launch_bounds__(256) void encoder_kernel(const float* __restrict__ x,
                                                      const float* __restrict__ W,
                                                      const float* __restrict__ b,
                                                      __half* __restrict__ Ph) {
    int d = threadIdx.x;
    float w[13];
#pragma unroll
    for (int k = 0; k < 13; k++) w[k] = W[k * D + d];
    float bb = b[d];
    __shared__ float xs[26];
    for (int n = blockIdx.x * 2; n < N_NODES; n += gridDim.x * 2) {
        __syncthreads();
        if (d < 26) {
            int nn = n + d / 13;
            if (nn < N_NODES) xs[d] = x[(size_t)nn * 13 + (d % 13)];
        }
        __syncthreads();
        float a0 = bb;
#pragma unroll
        for (int k = 0; k < 13; k++) a0 = fmaf(xs[k], w[k], a0);
        Ph[(size_t)n * D + d] = __float2half_rn(a0);
        if (n + 1 < N_NODES) {
            float a1 = bb;
#pragma unroll
            for (int k = 0; k < 13; k++) a1 = fmaf(xs[13 + k], w[k], a1);
            Ph[(size_t)(n + 1) * D + d] = __float2half_rn(a1);
        }
    }
}

// ---------------- weight pre-convert, smem tile-transposed ----------------
__global__ void prep_weights2_kernel(const float* __restrict__ relW,
                                     const float* __restrict__ rootW) {
    __shared__ float tile[32][33];
    int layer = blockIdx.z;
    int k0 = blockIdx.x * 32, n0 = blockIdx.y * 32;
    int tx = threadIdx.x, ty = threadIdx.y;
    const float* src = (k0 < KREL)
        ? relW + ((size_t)layer * KREL + k0) * D + n0
        : rootW + ((size_t)layer * D + (k0 - KREL)) * D + n0;
#pragma unroll
    for (int i = 0; i < 32; i += 8)
        tile[ty + i][tx] = src[(size_t)(ty + i) * D + tx];
    __syncthreads();
    size_t base = ((size_t)layer * D + n0) * KTOT + (size_t)k0;
#pragma unroll
    for (int i = 0; i < 32; i += 8) {
        int n = ty + i;
        g_Bh[base + (size_t)n * KTOT + tx] = __float2half_rn(tile[tx][n]);
    }
}
__global__ void prep_g_kernel(const float* __restrict__ gw1,
                              const float* __restrict__ gw2) {
    long u = (long)blockIdx.x * blockDim.x + threadIdx.x;
    if (u >= 2L * D * D) return;
    int w = (int)(u / (D * D));
    int rr = (int)(u % (D * D));
    int n = rr / D, k = rr % D;
    const float* W = w ? gw2 : gw1;
    g_Gh[u] = __float2half_rn(W[k * D + n]);
}

// ---------------- generic zero ----------------
__global__ void zero_kernel(float4* p, long n4) {
    long i = (long)blockIdx.x * blockDim.x + threadIdx.x;
    if (i < n4) p[i] = make_float4(0.f, 0.f, 0.f, 0.f);
}

// ---------------- mma.sync fp16 GEMM (layer kernel), k64 super-chunks, 2-stage ----
// EPI 0 only: v = C + bias + hold; prelu; row-l2norm -> Cout (fp16)
template <int EPI, int WM>
__global__ __launch_bounds__(WM * 128, 1) void mgemm_kernel(
    const __half* __restrict__ A1, int lda1, int splitK,
    const __half* __restrict__ A2, int lda2,
    const __half* __restrict__ Bhp, int Kb,
    int M, int K, int Moff,
    const float* __restrict__ bias,
    const float* __restrict__ prelu_a,
    const __half* __restrict__ HoldH,
    __half* __restrict__ CoutH) {
    constexpr int NT = WM * 128;
    constexpr int TM = WM * 32;
    constexpr int A_STG = TM * 128;
    constexpr int STG_SZ = A_STG + 32768;
    extern __shared__ char smem[];
    const uint32_t sb = s2u(smem);
    const int tid = threadIdx.x;
    const int wid = tid >> 5, lane = tid & 31;
    const int warpM = wid >> 2, warpN = wid & 3;
    const int m0 = Moff + blockIdx.x * TM;

    float acc[2][8][4];
#pragma unroll
    for (int m = 0; m < 2; m++)
#pragma unroll
        for (int n = 0; n < 8; n++)
#pragma unroll
            for (int j = 0; j < 4; j++) acc[m][n][j] = 0.f;

    const int nsup = K >> 6;

    auto ldA = [&](int t, int s) {
        int kc = t << 6;
        const __half* Ap; int la, kk;
        if (kc < splitK) { Ap = A1; la = lda1; kk = kc; }
        else             { Ap = A2; la = lda2; kk = kc - splitK; }
        int r = tid >> 2, q = tid & 3;
        int grow = m0 + r; if (grow > M - 1) grow = M - 1;
        const char* src = (const char*)Ap + ((size_t)grow * la + kk) * 2 + q * 32;
        uint32_t sw = (uint32_t)(r & 7);
        uint32_t dst = sb + (uint32_t)s * STG_SZ + (uint32_t)r * 128;
        cpasync16(dst + ((((uint32_t)(2 * q)) ^ sw) * 16), src);
        cpasync16(dst + ((((uint32_t)(2 * q + 1)) ^ sw) * 16), src + 16);
    };
    auto ldB = [&](int t, int s) {
        int kc = t << 6;
        uint32_t bbase = sb + (uint32_t)s * STG_SZ + (uint32_t)A_STG;
        for (int idx = tid; idx < 2048; idx += NT) {
            int row = idx >> 3, j = idx & 7;
            const char* src = (const char*)Bhp + ((size_t)row * Kb + kc) * 2 + j * 16;
            uint32_t sw = (uint32_t)(row & 7);
            cpasync16(bbase + (uint32_t)row * 128 + ((((uint32_t)j) ^ sw) * 16), src);
        }
    };
    auto domma = [&](int s) {
        uint32_t abase = sb + (uint32_t)s * STG_SZ;
        uint32_t bbase = abase + (uint32_t)A_STG;
        int arow_l = lane & 15, asel = lane >> 4;
        int brow_l = ((lane >> 4) << 3) + (lane & 7);
        int bsel = (lane >> 3) & 1;
#pragma unroll
        for (int ks = 0; ks < 4; ks++) {
            uint32_t Af[2][4];
#pragma unroll
            for (int m = 0; m < 2; m++) {
                int row = warpM * 32 + m * 16 + arow_l;
                uint32_t sw7 = (uint32_t)(row & 7);
                ldsm4(Af[m][0], Af[m][1], Af[m][2], Af[m][3],
                      abase + (uint32_t)row * 128 +
                          ((((uint32_t)(2 * ks + asel)) ^ sw7) * 16));
            }
#pragma unroll
            for (int nb = 0; nb < 4; nb++) {
                int row = warpN * 64 + nb * 16 + brow_l;
                uint32_t sw7 = (uint32_t)(row & 7);
                uint32_t bh_[4];
                ldsm4(bh_[0], bh_[1], bh_[2], bh_[3],
                      bbase + (uint32_t)row * 128 +
                          ((((uint32_t)(2 * ks + bsel)) ^ sw7) * 16));
#pragma unroll
                for (int m = 0; m < 2; m++) {
#pragma unroll
                    for (int j = 0; j < 2; j++)
                        mma16816(acc[m][nb * 2 + j], Af[m], bh_ + 2 * j);
                }
            }
        }
    };

    ldA(0, 0); ldB(0, 0); CP_COMMIT();
    if (nsup > 1) { ldA(1, 1); ldB(1, 1); }
    CP_COMMIT();
    for (int t = 0; t < nsup; t++) {
        if (t + 1 < nsup) CP_WAITG1();
        else              CP_WAITG0();
        __syncthreads();
        domma(t & 1);
        __syncthreads();
        if (t + 2 < nsup) { ldA(t + 2, t & 1); ldB(t + 2, t & 1); }
        CP_COMMIT();
    }

    // ---- fused epilogue (EPI 0) ----
    int tq = lane >> 2, tr = lane & 3;
    {
        float aP = prelu_a[0];
        float ssA[2][2];
#pragma unroll
        for (int m = 0; m < 2; m++) {
            int rloc0 = warpM * 32 + m * 16 + tq;
            int row0 = m0 + rloc0, row1 = row0 + 8;
            float s0 = 0.f, s1 = 0.f;
#pragma unroll
            for (int nf = 0; nf < 8; nf++) {
                int col = warpN * 64 + nf * 8 + tr * 2;
                float b0 = bias[col], b1 = bias[col + 1];
                float* C = acc[m][nf];
                if (row0 < M) {
                    size_t o = (size_t)row0 * D + col;
                    float2 hh = hf22(*(const uint32_t*)((const char*)HoldH + o * 2));
                    float v0 = C[0] + b0 + hh.x; v0 = v0 > 0.f ? v0 : aP * v0;
                    float v1 = C[1] + b1 + hh.y; v1 = v1 > 0.f ? v1 : aP * v1;
                    C[0] = v0; C[1] = v1; s0 += v0 * v0 + v1 * v1;
                }
                if (row1 < M) {
                    size_t o = (size_t)row1 * D + col;
                    float2 hh = hf22(*(const uint32_t*)((const char*)HoldH + o * 2));
                    float v2 = C[2] + b0 + hh.x; v2 = v2 > 0.f ? v2 : aP * v2;
                    float v3 = C[3] + b1 + hh.y; v3 = v3 > 0.f ? v3 : aP * v3;
                    C[2] = v2; C[3] = v3; s1 += v2 * v2 + v3 * v3;
                }
            }
            s0 += __shfl_xor_sync(0xffffffffu, s0, 1);
            s0 += __shfl_xor_sync(0xffffffffu, s0, 2);
            s1 += __shfl_xor_sync(0xffffffffu, s1, 1);
            s1 += __shfl_xor_sync(0xffffffffu, s1, 2);
            ssA[m][0] = s0; ssA[m][1] = s1;
        }
        __syncthreads();
        float* rsum = (float*)smem;
        if (tr == 0) {
#pragma unroll
            for (int m = 0; m < 2; m++) {
                int rloc0 = warpM * 32 + m * 16 + tq;
                rsum[rloc0 * 4 + warpN] = ssA[m][0];
                rsum[(rloc0 + 8) * 4 + warpN] = ssA[m][1];
            }
        }
        __syncthreads();
#pragma unroll
        for (int m = 0; m < 2; m++) {
            int rloc0 = warpM * 32 + m * 16 + tq;
            float t0 = rsum[rloc0 * 4 + 0] + rsum[rloc0 * 4 + 1] +
                       rsum[rloc0 * 4 + 2] + rsum[rloc0 * 4 + 3];
            float t1 = rsum[(rloc0 + 8) * 4 + 0] + rsum[(rloc0 + 8) * 4 + 1] +
                       rsum[(rloc0 + 8) * 4 + 2] + rsum[(rloc0 + 8) * 4 + 3];
            float inv0 = 1.f / fmaxf(sqrtf(t0), 1e-12f);
            float inv1 = 1.f / fmaxf(sqrtf(t1), 1e-12f);
            int row0 = m0 + rloc0, row1 = row0 + 8;
#pragma unroll
            for (int nf = 0; nf < 8; nf++) {
                int col = warpN * 64 + nf * 8 + tr * 2;
                float* C = acc[m][nf];
                if (row0 < M) {
                    size_t o = (size_t)row0 * D + col;
                    *(uint32_t*)((char*)CoutH + o * 2) =
                        packh(__float2half_rn(C[0] * inv0), __float2half_rn(C[1] * inv0));
                }
                if (row1 < M) {
                    size_t o = (size_t)row1 * D + col;
                    *(uint32_t*)((char*)CoutH + o * 2) =
                        packh(__float2half_rn(C[2] * inv1), __float2half_rn(C[3] * inv1));
                }
            }
        }
    }
}

#define TS4 (2 * (128 * 128 + 32768))   /* 98304 */
#define TS3 (2 * (96 * 128 + 32768))    /* 90112 */

// ---------------- fused gp1+gp2 kernel: pooled += (relu(h@G1+b1))@G2 + b2 ---------
// Phase 1: C = h @ G1 (K=256); epilogue writes relu(C+b1) to smem A' (fp16, same
// swizzled chunk layout ldsm reads). Phase 2: C = A' @ G2; epilogue pools.
template <int WM>
__global__ __launch_bounds__(WM * 128, 1) void gp_fused_kernel(
    const __half* __restrict__ Ph,
    const __half* __restrict__ G1, const __half* __restrict__ G2,
    const float* __restrict__ b1, const float* __restrict__ b2,
    int M, int Moff,
    const void* __restrict__ bat,
    float* __restrict__ pooled) {
    constexpr int NT = WM * 128;
    constexpr int TM = WM * 32;
    constexpr int A_STG = TM * 128;
    constexpr int STG_SZ = A_STG + 32768;
    constexpr int A2_SZ = TM * 512;           // A' tile: TM rows x 256 cols fp16
    extern __shared__ char smem[];
    const uint32_t sb = s2u(smem);
    const int tid = threadIdx.x;
    const int wid = tid >> 5, lane = tid & 31;
    const int warpM = wid >> 2, warpN = wid & 3;
    const int m0 = Moff + blockIdx.x * TM;

    float acc[2][8][4];
#pragma unroll
    for (int m = 0; m < 2; m++)
#pragma unroll
        for (int n = 0; n < 8; n++)
#pragma unroll
            for (int j = 0; j < 4; j++) acc[m][n][j] = 0.f;

    auto ldA = [&](int t, int s) {
        int kc = t << 6;
        int r = tid >> 2, q = tid & 3;
        int grow = m0 + r; if (grow > M - 1) grow = M - 1;
        const char* src = (const char*)Ph + ((size_t)grow * D + kc) * 2 + q * 32;
        uint32_t sw = (uint32_t)(r & 7);
        uint32_t dst = sb + (uint32_t)s * STG_SZ + (uint32_t)r * 128;
        cpasync16(dst + ((((uint32_t)(2 * q)) ^ sw) * 16), src);
        cpasync16(dst + ((((uint32_t)(2 * q + 1)) ^ sw) * 16), src + 16);
    };
    auto ldBx = [&](const __half* Bp, int t, uint32_t bbase) {
        int kc = t << 6;
        for (int idx = tid; idx < 2048; idx += NT) {
            int row = idx >> 3, j = idx & 7;
            const char* src = (const char*)Bp + ((size_t)row * D + kc) * 2 + j * 16;
            uint32_t sw = (uint32_t)(row & 7);
            cpasync16(bbase + (uint32_t)row * 128 + ((((uint32_t)j) ^ sw) * 16), src);
        }
    };
    auto dommaX = [&](uint32_t abase, uint32_t bbase) {
        int arow_l = lane & 15, asel = lane >> 4;
        int brow_l = ((lane >> 4) << 3) + (lane & 7);
        int bsel = (lane >> 3) & 1;
#pragma unroll
        for (int ks = 0; ks < 4; ks++) {
            uint32_t Af[2][4];
#pragma unroll
            for (int m = 0; m < 2; m++) {
                int row = warpM * 32 + m * 16 + arow_l;
                uint32_t sw7 = (uint32_t)(row & 7);
                ldsm4(Af[m][0], Af[m][1], Af[m][2], Af[m][3],
                      abase + (uint32_t)row * 128 +
                          ((((uint32_t)(2 * ks + asel)) ^ sw7) * 16));
            }
#pragma unroll
            for (int nb = 0; nb < 4; nb++) {
                int row = warpN * 64 + nb * 16 + brow_l;
                uint32_t sw7 = (uint32_t)(row & 7);
                uint32_t bh_[4];
                ldsm4(bh_[0], bh_[1], bh_[2], bh_[3],
                      bbase + (uint32_t)row * 128 +
                          ((((uint32_t)(2 * ks + bsel)) ^ sw7) * 16));
#pragma unroll
                for (int m = 0; m < 2; m++) {
#pragma unroll
                    for (int j = 0; j < 2; j++)
                        mma16816(acc[m][nb * 2 + j], Af[m], bh_ + 2 * j);
                }
            }
        }
    };

    // ---- phase 1 mainloop: K=256, 4 super-chunks, 2-stage ----
    ldA(0, 0); ldBx(G1, 0, sb + 0 * STG_SZ + A_STG); CP_COMMIT();
    ldA(1, 1); ldBx(G1, 1, sb + 1 * STG_SZ + A_STG); CP_COMMIT();
    for (int t = 0; t < 4; t++) {
        if (t + 1 < 4) CP_WAITG1();
        else           CP_WAITG0();
        __syncthreads();
        dommaX(sb + (uint32_t)(t & 1) * STG_SZ, sb + (uint32_t)(t & 1) * STG_SZ + A_STG);
        __syncthreads();
        if (t + 2 < 4) { ldA(t + 2, t & 1); ldBx(G1, t + 2, sb + (uint32_t)(t & 1) * STG_SZ + A_STG); }
        CP_COMMIT();
    }

    // ---- epilogue 1: relu(C+b1) -> smem A' (chunk warpN), reset acc ----
    int tq = lane >> 2, tr = lane & 3;
#pragma unroll
    for (int m = 0; m < 2; m++) {
        int rl0 = warpM * 32 + m * 16 + tq;
        int rl1 = rl0 + 8;
#pragma unroll
        for (int nf = 0; nf < 8; nf++) {
            int col = warpN * 64 + nf * 8 + tr * 2;
            float bb0 = b1[col], bb1 = b1[col + 1];
            float* C = acc[m][nf];
            float v0 = fmaxf(C[0] + bb0, 0.f), v1 = fmaxf(C[1] + bb1, 0.f);
            float v2 = fmaxf(C[2] + bb0, 0.f), v3 = fmaxf(C[3] + bb1, 0.f);
            // A' layout: chunk warpN tile base = warpN*TM*128; slot = nf ^ (r&7); byte tr*4
            size_t cbase = (size_t)warpN * (TM * 128);
            *(uint32_t*)(smem + cbase + (size_t)rl0 * 128 +
                         (((uint32_t)nf ^ (uint32_t)(rl0 & 7)) * 16) + tr * 4) =
                packh(__float2half_rn(v0), __float2half_rn(v1));
            *(uint32_t*)(smem + cbase + (size_t)rl1 * 128 +
                         (((uint32_t)nf ^ (uint32_t)(rl1 & 7)) * 16) + tr * 4) =
                packh(__float2half_rn(v2), __float2half_rn(v3));
            C[0] = 0.f; C[1] = 0.f; C[2] = 0.f; C[3] = 0.f;
        }
    }

    // ---- phase 2 mainloop: C = A' @ G2 ----
    ldBx(G2, 0, sb + (uint32_t)A2_SZ);            CP_COMMIT();
    ldBx(G2, 1, sb + (uint32_t)A2_SZ + 32768u);   CP_COMMIT();
    for (int t = 0; t < 4; t++) {
        if (t + 1 < 4) CP_WAITG1();
        else           CP_WAITG0();
        __syncthreads();           // also publishes A' writes on t==0
        dommaX(sb + (uint32_t)(t * (TM * 128)),
               sb + (uint32_t)A2_SZ + (uint32_t)(t & 1) * 32768u);
        __syncthreads();
        if (t + 2 < 4) ldBx(G2, t + 2, sb + (uint32_t)A2_SZ + (uint32_t)(t & 1) * 32768u);
        CP_COMMIT();
    }

    // ---- epilogue 2: fused global_add_pool ----
#pragma unroll
    for (int m = 0; m < 2; m++) {
        int rloc0 = warpM * 32 + m * 16 + tq;
        int row0 = m0 + rloc0, row1 = row0 + 8;
        int b0g = 0, b1g = 0;
        if (row0 < M)
            b0g = g_idx64 ? (int)((const long long*)bat)[row0] : ((const int*)bat)[row0];
        if (row1 < M)
            b1g = g_idx64 ? (int)((const long long*)bat)[row1] : ((const int*)bat)[row1];
#pragma unroll
        for (int nf = 0; nf < 8; nf++) {
            int col = warpN * 64 + nf * 8 + tr * 2;
            float bb0 = b2[col], bb1 = b2[col + 1];
            float* C = acc[m][nf];
            if (row0 < M) {
                atomicAdd(pooled + (size_t)b0g * D + col,     C[0] + bb0);
                atomicAdd(pooled + (size_t)b0g * D + col + 1, C[1] + bb1);
            }
            if (row1 < M) {
                atomicAdd(pooled + (size_t)b1g * D + col,     C[2] + bb0);
                atomicAdd(pooled + (size_t)b1g * D + col + 1, C[3] + bb1);
            }
        }
    }
}

#define TSF4 131072   /* max(2*49152, 128*512 + 2*32768) */
#define TSF3 114688   /* max(2*45056, 96*512 + 2*32768) */

// ---------------- fp32 SIMT GEMM (small fc layers only) ----------------
#define BM 128
#define BN 128
#define BKK 16
template <int ACT>
__global__ __launch_bounds__(256) void gemm_kernel(
    const float* __restrict__ A, int lda,
    const float* __restrict__ B,
    float* __restrict__ C, int M, int N, int K,
    const float* __restrict__ bias) {
    __shared__ float As[BKK][BM + 1];
    __shared__ float Bs[BKK][BN];
    int tid = threadIdx.x;
    int m0 = blockIdx.y * BM;
    int n0 = blockIdx.x * BN;
    int tm = (tid / 16) * 8;
    int tn = (tid % 16) * 8;
    float acc[8][8];
#pragma unroll
    for (int i = 0; i < 8; i++)
#pragma unroll
        for (int j = 0; j < 8; j++) acc[i][j] = 0.f;
    for (int kt = 0; kt < K; kt += BKK) {
#pragma unroll
        for (int f = tid; f < (BM * BKK / 4); f += 256) {
            int row = f >> 2;
            int c4 = (f & 3) * 4;
            float4 v = make_float4(0.f, 0.f, 0.f, 0.f);
            int grow = m0 + row;
            if (grow < M) v = *(const float4*)(A + (long)grow * lda + kt + c4);
            As[c4 + 0][row] = v.x; As[c4 + 1][row] = v.y;
            As[c4 + 2][row] = v.z; As[c4 + 3][row] = v.w;
        }
#pragma unroll
        for (int f = tid; f < (BKK * BN / 4); f += 256) {
            int kr = f >> 5;
            int c4 = (f & 31) * 4;
            *(float4*)&Bs[kr][c4] = *(const float4*)(B + (long)(kt + kr) * N + n0 + c4);
        }
        __syncthreads();
#pragma unroll
        for (int k = 0; k < BKK; k++) {
            float a[8], b[8];
#pragma unroll
            for (int i = 0; i < 8; i++) a[i] = As[k][tm + i];
#pragma unroll
            for (int j = 0; j < 8; j++) b[j] = Bs[k][tn + j];
#pragma unroll
            for (int i = 0; i < 8; i++)
#pragma unroll
                for (int j = 0; j < 8; j++) acc[i][j] = fmaf(a[i], b[j], acc[i][j]);
        }
        __syncthreads();
    }
#pragma unroll
    for (int i = 0; i < 8; i++) {
        int grow = m0 + tm + i;
        if (grow >= M) break;
        long base = (long)grow * N + n0 + tn;
#pragma unroll
        for (int j4 = 0; j4 < 8; j4 += 4) {
            float4 v;
            float t0 = acc[i][j4 + 0] + bias[n0 + tn + j4 + 0];
            float t1 = acc[i][j4 + 1] + bias[n0 + tn + j4 + 1];
            float t2 = acc[i][j4 + 2] + bias[n0 + tn + j4 + 2];
            float t3 = acc[i][j4 + 3] + bias[n0 + tn + j4 + 3];
            if (ACT == 1) {
                t0 = fmaxf(t0, 0.f); t1 = fmaxf(t1, 0.f);
                t2 = fmaxf(t2, 0.f); t3 = fmaxf(t3, 0.f);
            }
            v.x = t0; v.y = t1; v.z = t2; v.w = t3;
            *(float4*)(C + base + j4) = v;
        }
    }
}

// ---------------- final GEMV ----------------
__global__ void out_gemv_kernel(const float* __restrict__ z2,
                                const float* __restrict__ w,
                                const float* __restrict__ b,
                                float* __restrict__ out) {
    int g = blockIdx.x * blockDim.x + threadIdx.x;
    int row = g >> 5;
    int lane = g & 31;
    if (row >= NUM_GRAPHS) return;
    float acc = 0.f;
#pragma unroll
    for (int k = lane; k < 512; k += 32) acc = fmaf(z2[(long)row * 512 + k], w[k], acc);
#pragma unroll
    for (int o = 16; o > 0; o >>= 1) acc += __shfl_xor_sync(0xffffffffu, acc, o);
    if (lane == 0) out[row] = fmaxf(acc + b[0], 0.f);
}

// ---------------- host ----------------
extern "C" void kernel_launch(void* const* d_in, const int* in_sizes, int n_in,
                              void* d_out, int out_size) {
    const float* x      = (const float*)d_in[0];
    const void*  ei     = d_in[1];
    const void*  et     = d_in[2];
    const void*  bat    = d_in[3];
    const float* enc_W  = (const float*)d_in[4];
    const float* enc_b  = (const float*)d_in[5];
    const float* prelua = (const float*)d_in[6];
    const float* rel_W  = (const float*)d_in[7];
    const float* root_W = (const float*)d_in[8];
    const float* conv_b = (const float*)d_in[9];
    const float* gp_W1  = (const float*)d_in[10];
    const float* gp_b1  = (const float*)d_in[11];
    const float* gp_W2  = (const float*)d_in[12];
    const float* gp_b2  = (const float*)d_in[13];
    const float* fc_W1  = (const float*)d_in[14];
    const float* fc_b1  = (const float*)d_in[15];
    const float* fc_W2  = (const float*)d_in[16];
    const float* fc_b2  = (const float*)d_in[17];
    const float* out_W  = (const float*)d_in[18];
    const float* out_b  = (const float*)d_in[19];
    float* out = (float*)d_out;

    float *P, *Z1, *Z2;
    __half *Af, *Bh, *Gh, *Ph0, *Ph1;
    cudaGetSymbolAddress((void**)&Af, g_Af);
    cudaGetSymbolAddress((void**)&P, g_pooled);
    cudaGetSymbolAddress((void**)&Z1, g_z1);
    cudaGetSymbolAddress((void**)&Z2, g_z2);
    cudaGetSymbolAddress((void**)&Bh, g_Bh);
    cudaGetSymbolAddress((void**)&Gh, g_Gh);
    cudaGetSymbolAddress((void**)&Ph0, g_Ph0);
    cudaGetSymbolAddress((void**)&Ph1, g_Ph1);

    cudaFuncSetAttribute(mgemm_kernel<0, 4>, cudaFuncAttributeMaxDynamicSharedMemorySize, TS4);
    cudaFuncSetAttribute(mgemm_kernel<0, 3>, cudaFuncAttributeMaxDynamicSharedMemorySize, TS3);
    cudaFuncSetAttribute(gp_fused_kernel<4>, cudaFuncAttributeMaxDynamicSharedMemorySize, TSF4);
    cudaFuncSetAttribute(gp_fused_kernel<3>, cudaFuncAttributeMaxDynamicSharedMemorySize, TSF3);

    detect_idx_kernel<<<1, 32>>>(ei);
    prep_weights2_kernel<<<dim3(KTOT / 32, D / 32, N_LAYERS), dim3(32, 8)>>>(rel_W, root_W);
    prep_g_kernel<<<(2 * D * D + 255) / 256, 256>>>(gp_W1, gp_W2);
    encoder_kernel<<<1480, 256>>>(x, enc_W, enc_b, Ph0);

    // CSR build (edge structure is loop-invariant)
    hist_zero_kernel<<<(NPAIR + 255) / 256, 256>>>();
    hist_build_kernel<<<(N_EDGES + 255) / 256, 256>>>(ei, et, N_EDGES);
    scan1_kernel<<<NSB, SCAN_B>>>();
    scan2_kernel<<<1, 1024>>>();
    scan3_kernel<<<(NPAIR + 255) / 256, 256>>>();
    place_kernel<<<(N_EDGES + 255) / 256, 256>>>(ei, et, N_EDGES);

    const int agg_blocks = (NPAIR + 7) / 8;

    __half *PhI = Ph0, *PhO = Ph1;
    for (int i = 0; i < N_LAYERS; i++) {
        const __half* Bhi = Bh + (size_t)i * D * KTOT;
        const float* cbi = conv_b + (size_t)i * D;
        agg_kernel<<<agg_blocks, 256>>>(PhI);
        mgemm_kernel<0, 4><<<TILES4, 512, TS4>>>(
            Af, KREL, KREL, PhI, D, Bhi, KTOT,
            N_NODES, KTOT, 0, cbi, prelua, PhI, PhO);
        mgemm_kernel<0, 3><<<TILES3, 384, TS3>>>(
            Af, KREL, KREL, PhI, D, Bhi, KTOT,
            N_NODES, KTOT, OFF4, cbi, prelua, PhI, PhO);
        __half* tb = PhI; PhI = PhO; PhO = tb;
    }
    // PhI = final h (fp16)

    // fused gp1+gp2 with pooled accumulation
    zero_kernel<<<(NUM_GRAPHS * D / 4 + 255) / 256, 256>>>((float4*)P, NUM_GRAPHS * D / 4);
    gp_fused_kernel<4><<<TILES4, 512, TSF4>>>(
        PhI, Gh, Gh + (size_t)D * D, gp_b1, gp_b2, N_NODES, 0, bat, P);
    gp_fused_kernel<3><<<TILES3, 384, TSF3>>>(
        PhI, Gh, Gh + (size_t)D * D, gp_b1, gp_b2, N_NODES, OFF4, bat, P);

    // fc stack (tiny — fp32 SIMT)
    gemm_kernel<1><<<dim3(1024 / BN, NUM_GRAPHS / BM), 256>>>(
        P, D, fc_W1, Z1, NUM_GRAPHS, 1024, D, fc_b1);
    gemm_kernel<1><<<dim3(512 / BN, NUM_GRAPHS / BM), 256>>>(
        Z1, 1024, fc_W2, Z2, NUM_GRAPHS, 512, 1024, fc_b2);
    out_gemv_kernel<<<(NUM_GRAPHS * 32 + 255) / 256, 256>>>(Z2, out_W, out_b, out);

    (void)in_sizes; (void)n_in; (void)out_size;
}